// round 2
// baseline (speedup 1.0000x reference)
#include <cuda_runtime.h>
#include <math.h>
#include <float.h>

// ---------------- problem constants ----------------
#define BATCH   4
#define QLEN    128
#define HDIM    4096
#define NHEAD   32
#define NKVH    8
#define DHEAD   128
#define KVDIM   1024           // NKVH * DHEAD
#define TOK     512            // BATCH * QLEN
#define NQK     4096           // quantized tokens
#define RESLEN  128            // fp32 past tokens
#define KVSEQ   4352           // NQK + RESLEN + QLEN
#define PASTLEN 4224           // NQK + RESLEN  (also kv_seq - q_len)
#define NEGF    (-3.402823466e38f)

// ---------------- scratch (device globals; no allocs allowed) ----------------
__device__ float g_qlin[TOK * HDIM];              // 512 x 4096
__device__ float g_klin[TOK * KVDIM];             // 512 x 1024
__device__ float g_vlin[TOK * KVDIM];             // 512 x 1024
__device__ float g_q   [BATCH * NHEAD * QLEN * DHEAD];     // [b][h][t][d]
__device__ float g_kall[BATCH * NKVH * KVSEQ * DHEAD];     // [b][kvh][n][d]
__device__ float g_vall[BATCH * NKVH * KVSEQ * DHEAD];     // [b][kvh][n][d]
__device__ float g_p   [BATCH * NHEAD * QLEN * KVSEQ];     // attn probs
__device__ float g_ao  [TOK * HDIM];              // attention out, token-major

// ---------------- generic SGEMM:  C[m][n] = sum_k A[m][k]*B[n][k] (+bias[n]) ----
// A: MxK row-major, B: NxK row-major. M,N multiples of 128; K multiple of 8.
__global__ __launch_bounds__(256) void sgemm_nt(
    const float* __restrict__ A, const float* __restrict__ Bw,
    const float* __restrict__ bias, float* __restrict__ C,
    int M, int N, int K)
{
    __shared__ float As[8][128];
    __shared__ float Bs[8][128];
    const int tid  = threadIdx.x;
    const int ty   = tid >> 4;
    const int tx   = tid & 15;
    const int bm   = blockIdx.y << 7;
    const int bn   = blockIdx.x << 7;
    const int lrow = tid >> 1;
    const int lcol = (tid & 1) << 2;
    const float* Ap = A  + (size_t)(bm + lrow) * K + lcol;
    const float* Bp = Bw + (size_t)(bn + lrow) * K + lcol;

    float acc[8][8];
#pragma unroll
    for (int i = 0; i < 8; i++)
#pragma unroll
        for (int j = 0; j < 8; j++) acc[i][j] = 0.f;

    for (int k0 = 0; k0 < K; k0 += 8) {
        float4 a4 = *(const float4*)(Ap + k0);
        float4 b4 = *(const float4*)(Bp + k0);
        As[lcol+0][lrow] = a4.x; As[lcol+1][lrow] = a4.y;
        As[lcol+2][lrow] = a4.z; As[lcol+3][lrow] = a4.w;
        Bs[lcol+0][lrow] = b4.x; Bs[lcol+1][lrow] = b4.y;
        Bs[lcol+2][lrow] = b4.z; Bs[lcol+3][lrow] = b4.w;
        __syncthreads();
#pragma unroll
        for (int k = 0; k < 8; k++) {
            float a[8], b[8];
            *(float4*)&a[0] = *(const float4*)&As[k][ty*4];
            *(float4*)&a[4] = *(const float4*)&As[k][64 + ty*4];
            *(float4*)&b[0] = *(const float4*)&Bs[k][tx*4];
            *(float4*)&b[4] = *(const float4*)&Bs[k][64 + tx*4];
#pragma unroll
            for (int i = 0; i < 8; i++)
#pragma unroll
                for (int j = 0; j < 8; j++)
                    acc[i][j] = fmaf(a[i], b[j], acc[i][j]);
        }
        __syncthreads();
    }

#pragma unroll
    for (int i = 0; i < 8; i++) {
        int r = bm + ((i < 4) ? (ty*4 + i) : (64 + ty*4 + i - 4));
#pragma unroll
        for (int jh = 0; jh < 2; jh++) {
            int c = bn + (jh ? (64 + tx*4) : (tx*4));
            float4 v;
            v.x = acc[i][jh*4+0]; v.y = acc[i][jh*4+1];
            v.z = acc[i][jh*4+2]; v.w = acc[i][jh*4+3];
            if (bias) {
                v.x += bias[c+0]; v.y += bias[c+1];
                v.z += bias[c+2]; v.w += bias[c+3];
            }
            *(float4*)(C + (size_t)r * N + c) = v;
        }
    }
}

// ---------------- RoPE Q: qlin (token-major) -> g_q [b][h][t][d] --------------
__global__ __launch_bounds__(256) void rope_q_kernel()
{
    int idx = blockIdx.x * 256 + threadIdx.x;      // over 512*4096
    int d = idx & 127;
    int t = (idx >> 7) & 127;
    int h = (idx >> 14) & 31;
    int b = idx >> 19;
    size_t base = ((size_t)(b * QLEN + t)) * HDIM + (size_t)h * DHEAD;
    int i = d & 63;
    float inv = 1.0f / powf(1.0e6f, (float)(2 * i) / 128.0f);
    float ang = (float)(PASTLEN + t) * inv;
    float s, c;
    sincosf(ang, &s, &c);
    float x  = g_qlin[base + d];
    float xo = g_qlin[base + ((d < 64) ? d + 64 : d - 64)];
    float out = (d < 64) ? (x * c - xo * s) : (x * c + xo * s);
    g_q[idx] = out;
}

// ---------------- RoPE K + V-new: into rows [PASTLEN, KVSEQ) of caches --------
__global__ __launch_bounds__(256) void rope_k_kernel()
{
    int idx = blockIdx.x * 256 + threadIdx.x;      // over 4*8*128*128
    int d   = idx & 127;
    int t   = (idx >> 7) & 127;
    int kvh = (idx >> 14) & 7;
    int b   = idx >> 17;
    size_t base = ((size_t)(b * QLEN + t)) * KVDIM + (size_t)kvh * DHEAD;
    int i = d & 63;
    float inv = 1.0f / powf(1.0e6f, (float)(2 * i) / 128.0f);
    float ang = (float)(PASTLEN + t) * inv;
    float s, c;
    sincosf(ang, &s, &c);
    float x  = g_klin[base + d];
    float xo = g_klin[base + ((d < 64) ? d + 64 : d - 64)];
    float out = (d < 64) ? (x * c - xo * s) : (x * c + xo * s);
    g_kall[(((size_t)(b * NKVH + kvh)) * KVSEQ + PASTLEN + t) * DHEAD + d] = out;
    // V new (no rope) — same indexing, reuse the thread
    g_vall[(((size_t)(b * NKVH + kvh)) * KVSEQ + PASTLEN + t) * DHEAD + d] =
        g_vlin[base + d];
}

// ---------------- copy fp32 past K/V into rows [NQK, NQK+RESLEN) --------------
__global__ __launch_bounds__(256) void past_copy_kernel(
    const float* __restrict__ kfp, const float* __restrict__ vfp)
{
    int idx = blockIdx.x * 256 + threadIdx.x;      // over 32*128*128
    int d  = idx & 127;
    int r  = (idx >> 7) & 127;
    int bk = idx >> 14;
    size_t src = ((size_t)bk * RESLEN + r) * DHEAD + d;
    size_t dst = ((size_t)bk * KVSEQ + NQK + r) * DHEAD + d;
    if (blockIdx.y == 0) g_kall[dst] = kfp[src];
    else                 g_vall[dst] = vfp[src];
}

// ---------------- dequant 2-bit K (stored d-major, transpose to n-major) ------
__global__ __launch_bounds__(256) void dequant_k_kernel(
    const int* __restrict__ kq, const float* __restrict__ ks,
    const float* __restrict__ km)
{
    int idx = blockIdx.x * 256 + threadIdx.x;      // over 32*4096*128
    int d  = idx & 127;
    int n  = (idx >> 7) & 4095;
    int bk = idx >> 19;
    unsigned word = (unsigned)kq[((size_t)bk * DHEAD + d) * (NQK / 16) + (n >> 4)];
    float code = (float)((word >> ((n & 15) * 2)) & 3u);
    size_t sidx = ((size_t)bk * DHEAD + d) * (NQK / 64) + (n >> 6);
    g_kall[((size_t)bk * KVSEQ + n) * DHEAD + d] = code * ks[sidx] + km[sidx];
}

// ---------------- dequant 2-bit V (stored n-major, packed along d) ------------
__global__ __launch_bounds__(256) void dequant_v_kernel(
    const int* __restrict__ vq, const float* __restrict__ vs,
    const float* __restrict__ vm)
{
    int idx = blockIdx.x * 256 + threadIdx.x;      // over 32*4096*128
    int d  = idx & 127;
    int n  = (idx >> 7) & 4095;
    int bk = idx >> 19;
    unsigned word = (unsigned)vq[((size_t)bk * NQK + n) * (DHEAD / 16) + (d >> 4)];
    float code = (float)((word >> ((d & 15) * 2)) & 3u);
    size_t sidx = ((size_t)bk * NQK + n) * (DHEAD / 64) + (d >> 6);
    g_vall[((size_t)bk * KVSEQ + n) * DHEAD + d] = code * vs[sidx] + vm[sidx];
}

// ---------------- attention scores: S = Q K^T / sqrt(D) + mask ----------------
__global__ __launch_bounds__(256) void attn_scores_kernel()
{
    const int bh  = blockIdx.y;                  // 0..127 == b*NHEAD + h
    const int b   = bh >> 5, h = bh & 31, kvh = h >> 2;
    const int bn  = blockIdx.x << 7;             // n-tile base
    const float* A  = g_q + (size_t)bh * QLEN * DHEAD;
    const float* Bp = g_kall + ((size_t)(b * NKVH + kvh) * KVSEQ + bn) * DHEAD;

    __shared__ float As[8][128];
    __shared__ float Bs[8][128];
    const int tid  = threadIdx.x;
    const int ty   = tid >> 4, tx = tid & 15;
    const int lrow = tid >> 1, lcol = (tid & 1) << 2;

    float acc[8][8];
#pragma unroll
    for (int i = 0; i < 8; i++)
#pragma unroll
        for (int j = 0; j < 8; j++) acc[i][j] = 0.f;

    for (int k0 = 0; k0 < DHEAD; k0 += 8) {
        float4 a4 = *(const float4*)(A  + (size_t)lrow * DHEAD + k0 + lcol);
        float4 b4 = *(const float4*)(Bp + (size_t)lrow * DHEAD + k0 + lcol);
        As[lcol+0][lrow] = a4.x; As[lcol+1][lrow] = a4.y;
        As[lcol+2][lrow] = a4.z; As[lcol+3][lrow] = a4.w;
        Bs[lcol+0][lrow] = b4.x; Bs[lcol+1][lrow] = b4.y;
        Bs[lcol+2][lrow] = b4.z; Bs[lcol+3][lrow] = b4.w;
        __syncthreads();
#pragma unroll
        for (int k = 0; k < 8; k++) {
            float a[8], bb[8];
            *(float4*)&a[0]  = *(const float4*)&As[k][ty*4];
            *(float4*)&a[4]  = *(const float4*)&As[k][64 + ty*4];
            *(float4*)&bb[0] = *(const float4*)&Bs[k][tx*4];
            *(float4*)&bb[4] = *(const float4*)&Bs[k][64 + tx*4];
#pragma unroll
            for (int i = 0; i < 8; i++)
#pragma unroll
                for (int j = 0; j < 8; j++)
                    acc[i][j] = fmaf(a[i], bb[j], acc[i][j]);
        }
        __syncthreads();
    }

    const float sc = 0.08838834764831845f;       // 1/sqrt(128)
#pragma unroll
    for (int i = 0; i < 8; i++) {
        int r = (i < 4) ? (ty*4 + i) : (64 + ty*4 + i - 4);   // q row
#pragma unroll
        for (int jh = 0; jh < 2; jh++) {
            int c0 = bn + (jh ? (64 + tx*4) : (tx*4));
            float4 v;
            float tmp[4];
#pragma unroll
            for (int j = 0; j < 4; j++) {
                float s = acc[i][jh*4 + j] * sc;
                int n = c0 + j;
                if (n >= PASTLEN && (n - PASTLEN) > r) s = NEGF;
                tmp[j] = s;
            }
            v.x = tmp[0]; v.y = tmp[1]; v.z = tmp[2]; v.w = tmp[3];
            *(float4*)(g_p + ((size_t)bh * QLEN + r) * KVSEQ + c0) = v;
        }
    }
}

// ---------------- row softmax over KVSEQ=4352 (= 17*256) ----------------------
__global__ __launch_bounds__(256) void softmax_kernel()
{
    const int row = blockIdx.x;                  // 0..16383
    float* p = g_p + (size_t)row * KVSEQ;
    const int t = threadIdx.x;
    float v[17];
    float m = NEGF;
#pragma unroll
    for (int i = 0; i < 17; i++) {
        v[i] = p[t + i * 256];
        m = fmaxf(m, v[i]);
    }
    __shared__ float red[8];
#pragma unroll
    for (int o = 16; o > 0; o >>= 1) m = fmaxf(m, __shfl_xor_sync(0xffffffffu, m, o));
    if ((t & 31) == 0) red[t >> 5] = m;
    __syncthreads();
    float bm = red[0];
#pragma unroll
    for (int w = 1; w < 8; w++) bm = fmaxf(bm, red[w]);
    __syncthreads();

    float s = 0.f;
#pragma unroll
    for (int i = 0; i < 17; i++) {
        v[i] = expf(v[i] - bm);
        s += v[i];
    }
#pragma unroll
    for (int o = 16; o > 0; o >>= 1) s += __shfl_xor_sync(0xffffffffu, s, o);
    if ((t & 31) == 0) red[t >> 5] = s;
    __syncthreads();
    float tot = 0.f;
#pragma unroll
    for (int w = 0; w < 8; w++) tot += red[w];
    float inv = 1.0f / tot;
#pragma unroll
    for (int i = 0; i < 17; i++) p[t + i * 256] = v[i] * inv;
}

// ---------------- P @ V  -> g_ao token-major ----------------------------------
__global__ __launch_bounds__(256) void attn_pv_kernel()
{
    const int bh = blockIdx.x;                   // 0..127
    const int b = bh >> 5, h = bh & 31, kvh = h >> 2;
    const float* A  = g_p + (size_t)bh * QLEN * KVSEQ;
    const float* Bv = g_vall + (size_t)(b * NKVH + kvh) * KVSEQ * DHEAD;

    __shared__ float As[16][128];
    __shared__ float Bs[16][128];
    const int tid = threadIdx.x;
    const int ty  = tid >> 4, tx = tid & 15;
    const int arow = tid >> 1, ak = (tid & 1) << 3;
    const int bkrow = tid >> 4, bdcol = (tid & 15) << 3;

    float acc[8][8];
#pragma unroll
    for (int i = 0; i < 8; i++)
#pragma unroll
        for (int j = 0; j < 8; j++) acc[i][j] = 0.f;

    for (int k0 = 0; k0 < KVSEQ; k0 += 16) {
        float4 a0 = *(const float4*)(A + (size_t)arow * KVSEQ + k0 + ak);
        float4 a1 = *(const float4*)(A + (size_t)arow * KVSEQ + k0 + ak + 4);
        As[ak+0][arow] = a0.x; As[ak+1][arow] = a0.y;
        As[ak+2][arow] = a0.z; As[ak+3][arow] = a0.w;
        As[ak+4][arow] = a1.x; As[ak+5][arow] = a1.y;
        As[ak+6][arow] = a1.z; As[ak+7][arow] = a1.w;
        float4 b0 = *(const float4*)(Bv + (size_t)(k0 + bkrow) * DHEAD + bdcol);
        float4 b1 = *(const float4*)(Bv + (size_t)(k0 + bkrow) * DHEAD + bdcol + 4);
        *(float4*)&Bs[bkrow][bdcol]     = b0;
        *(float4*)&Bs[bkrow][bdcol + 4] = b1;
        __syncthreads();
#pragma unroll
        for (int k = 0; k < 16; k++) {
            float a[8], bb[8];
            *(float4*)&a[0]  = *(const float4*)&As[k][ty*4];
            *(float4*)&a[4]  = *(const float4*)&As[k][64 + ty*4];
            *(float4*)&bb[0] = *(const float4*)&Bs[k][tx*4];
            *(float4*)&bb[4] = *(const float4*)&Bs[k][64 + tx*4];
#pragma unroll
            for (int i = 0; i < 8; i++)
#pragma unroll
                for (int j = 0; j < 8; j++)
                    acc[i][j] = fmaf(a[i], bb[j], acc[i][j]);
        }
        __syncthreads();
    }

#pragma unroll
    for (int i = 0; i < 8; i++) {
        int r = (i < 4) ? (ty*4 + i) : (64 + ty*4 + i - 4);   // q row
#pragma unroll
        for (int jh = 0; jh < 2; jh++) {
            int c = (jh ? (64 + tx*4) : (tx*4));              // d col
            float4 v;
            v.x = acc[i][jh*4+0]; v.y = acc[i][jh*4+1];
            v.z = acc[i][jh*4+2]; v.w = acc[i][jh*4+3];
            *(float4*)(g_ao + ((size_t)(b * QLEN + r)) * HDIM
                             + (size_t)h * DHEAD + c) = v;
        }
    }
}

// ---------------- host launch --------------------------------------------------
extern "C" void kernel_launch(void* const* d_in, const int* in_sizes, int n_in,
                              void* d_out, int out_size)
{
    (void)in_sizes; (void)n_in; (void)out_size;
    const float* hs  = (const float*)d_in[0];
    const float* qw  = (const float*)d_in[1];
    const float* qb  = (const float*)d_in[2];
    const float* kw  = (const float*)d_in[3];
    const float* kb  = (const float*)d_in[4];
    const float* vw  = (const float*)d_in[5];
    const float* vb  = (const float*)d_in[6];
    const float* ow  = (const float*)d_in[7];
    const int*   kqt = (const int*)  d_in[8];
    const float* kst = (const float*)d_in[9];
    const float* kmt = (const float*)d_in[10];
    const float* kfp = (const float*)d_in[11];
    const int*   vq  = (const int*)  d_in[12];
    const float* vs  = (const float*)d_in[13];
    const float* vm  = (const float*)d_in[14];
    const float* vfp = (const float*)d_in[15];
    float* out = (float*)d_out;

    float *qlin, *klin, *vlin, *ao;
    cudaGetSymbolAddress((void**)&qlin, g_qlin);
    cudaGetSymbolAddress((void**)&klin, g_klin);
    cudaGetSymbolAddress((void**)&vlin, g_vlin);
    cudaGetSymbolAddress((void**)&ao,   g_ao);

    dim3 blk(256);

    // QKV projections (+bias)
    sgemm_nt<<<dim3(32, 4), blk>>>(hs, qw, qb, qlin, TOK, HDIM,  HDIM);
    sgemm_nt<<<dim3(8,  4), blk>>>(hs, kw, kb, klin, TOK, KVDIM, HDIM);
    sgemm_nt<<<dim3(8,  4), blk>>>(hs, vw, vb, vlin, TOK, KVDIM, HDIM);

    // RoPE + cache assembly
    rope_q_kernel<<<(TOK * HDIM) / 256, blk>>>();
    rope_k_kernel<<<(TOK * KVDIM) / 256, blk>>>();
    past_copy_kernel<<<dim3((32 * RESLEN * DHEAD) / 256, 2), blk>>>(kfp, vfp);
    dequant_k_kernel<<<(32 * NQK * DHEAD) / 256, blk>>>(kqt, kst, kmt);
    dequant_v_kernel<<<(32 * NQK * DHEAD) / 256, blk>>>(vq, vs, vm);

    // attention
    attn_scores_kernel<<<dim3(KVSEQ / 128, BATCH * NHEAD), blk>>>();
    softmax_kernel<<<BATCH * NHEAD * QLEN, blk>>>();
    attn_pv_kernel<<<BATCH * NHEAD, blk>>>();

    // output projection
    sgemm_nt<<<dim3(32, 4), blk>>>(ao, ow, nullptr, out, TOK, HDIM, HDIM);
}

// round 7
// speedup vs baseline: 1.9138x; 1.9138x over previous
#include <cuda_runtime.h>
#include <cuda_bf16.h>
#include <math.h>
#include <float.h>
#include <stdint.h>

// ---------------- problem constants ----------------
#define BATCH   4
#define QLEN    128
#define HDIM    4096
#define NHEAD   32
#define NKVH    8
#define DHEAD   128
#define KVDIM   1024
#define TOK     512
#define NQK     4096
#define RESLEN  128
#define KVSEQ   4352
#define PASTLEN 4224
#define NEGF    (-3.402823466e38f)

// ---------------- scratch ----------------
__device__ float g_qlin[TOK * HDIM];
__device__ float g_klin[TOK * KVDIM];
__device__ float g_vlin[TOK * KVDIM];
__device__ float g_q   [BATCH * NHEAD * QLEN * DHEAD];     // [bh][q][d]
__device__ float g_kall[BATCH * NKVH * KVSEQ * DHEAD];     // [bk][n][d]
__device__ float g_vt  [BATCH * NKVH * DHEAD * KVSEQ];     // [bk][d][n]
__device__ float g_p   [BATCH * NHEAD * QLEN * KVSEQ];
__device__ float g_ao  [TOK * HDIM];

// ---------------- HMMA helper (baseline PTX, works on compute_103) -----------
__device__ __forceinline__ void mma16816(float* c, const uint32_t* a, const uint32_t* b) {
    asm volatile(
        "mma.sync.aligned.m16n8k16.row.col.f32.bf16.bf16.f32 "
        "{%0,%1,%2,%3}, {%4,%5,%6,%7}, {%8,%9}, {%0,%1,%2,%3};"
        : "+f"(c[0]), "+f"(c[1]), "+f"(c[2]), "+f"(c[3])
        : "r"(a[0]), "r"(a[1]), "r"(a[2]), "r"(a[3]), "r"(b[0]), "r"(b[1]));
}

__device__ __forceinline__ uint32_t pack_bf16(float lo, float hi) {
    __nv_bfloat162 p(__float2bfloat16(lo), __float2bfloat16(hi));
    return *(uint32_t*)&p;
}

// smem: 4 tiles of 128 rows x 72 bf16 pitch (pad kills fragment-load conflicts)
#define PITCH 72
#define TILE_ELEMS (128 * PITCH)
#define S_TOTAL (4 * TILE_ELEMS * 2)      // 73728 bytes

// ---------------- generic split-bf16 HMMA GEMM --------------------------------
// C[m][n'] = scale * sum_k A[m][k]*B[n'][k] (+bias[n']) (+causal mask mode 1)
// mode 0: plain tiles at blockIdx           K = Kin
// mode 1: scores, bh=blockIdx.y, ntile=x    K = 128
// mode 2: PV, bh=blockIdx.y                 K = KVSEQ
__global__ __launch_bounds__(256) void gemm_mma(
    const float* __restrict__ Ain, const float* __restrict__ Bin,
    const float* __restrict__ bias, float* __restrict__ Cin,
    int lda, int ldb, int ldc, int Kin, int mode, float scale)
{
    extern __shared__ __nv_bfloat16 sm[];
    __nv_bfloat16* sAhi = sm;
    __nv_bfloat16* sAlo = sm + TILE_ELEMS;
    __nv_bfloat16* sBhi = sm + 2 * TILE_ELEMS;
    __nv_bfloat16* sBlo = sm + 3 * TILE_ELEMS;

    const int tid  = threadIdx.x;
    const int lane = tid & 31;
    const int wid  = tid >> 5;
    const int wm   = wid >> 2;          // 0..1
    const int wn   = wid & 3;           // 0..3

    const float* A;
    const float* B;
    float* C;
    int col0;
    if (mode == 0) {
        col0 = blockIdx.x * 128;
        A = Ain + (size_t)(blockIdx.y * 128) * lda;
        B = Bin + (size_t)col0 * ldb;
        C = Cin + (size_t)(blockIdx.y * 128) * ldc + col0;
    } else if (mode == 1) {
        int bh = blockIdx.y, b = bh >> 5, kvh = (bh & 31) >> 2;
        col0 = blockIdx.x * 128;
        A = g_q + (size_t)bh * (QLEN * DHEAD);
        B = g_kall + ((size_t)(b * NKVH + kvh) * KVSEQ + col0) * DHEAD;
        C = g_p + (size_t)bh * QLEN * KVSEQ + col0;
    } else {
        int bh = blockIdx.y, b = bh >> 5, h = bh & 31, kvh = h >> 2;
        col0 = 0;
        A = g_p + (size_t)bh * QLEN * KVSEQ;
        B = g_vt + (size_t)(b * NKVH + kvh) * DHEAD * KVSEQ;
        C = g_ao + (size_t)(b * QLEN) * HDIM + h * DHEAD;
    }

    float acc[4][4][4];
#pragma unroll
    for (int mt = 0; mt < 4; mt++)
#pragma unroll
        for (int nt = 0; nt < 4; nt++)
#pragma unroll
            for (int i = 0; i < 4; i++) acc[mt][nt][i] = 0.f;

    const int nchunks = Kin >> 6;
    for (int ch = 0; ch < nchunks; ch++) {
        const float* Ak = A + (ch << 6);
        const float* Bk = B + (ch << 6);
        // stage + fp32 -> bf16 hi/lo split
#pragma unroll
        for (int e = tid * 4; e < 8192; e += 1024) {
            int r = e >> 6, k = e & 63;
            int so = r * PITCH + k;
            float4 a = *(const float4*)(Ak + (size_t)r * lda + k);
            float hx = __bfloat162float(__float2bfloat16(a.x));
            float hy = __bfloat162float(__float2bfloat16(a.y));
            float hz = __bfloat162float(__float2bfloat16(a.z));
            float hw = __bfloat162float(__float2bfloat16(a.w));
            uint2 v;
            v.x = pack_bf16(hx, hy); v.y = pack_bf16(hz, hw);
            *(uint2*)&sAhi[so] = v;
            v.x = pack_bf16(a.x - hx, a.y - hy); v.y = pack_bf16(a.z - hz, a.w - hw);
            *(uint2*)&sAlo[so] = v;
            float4 b = *(const float4*)(Bk + (size_t)r * ldb + k);
            hx = __bfloat162float(__float2bfloat16(b.x));
            hy = __bfloat162float(__float2bfloat16(b.y));
            hz = __bfloat162float(__float2bfloat16(b.z));
            hw = __bfloat162float(__float2bfloat16(b.w));
            v.x = pack_bf16(hx, hy); v.y = pack_bf16(hz, hw);
            *(uint2*)&sBhi[so] = v;
            v.x = pack_bf16(b.x - hx, b.y - hy); v.y = pack_bf16(b.z - hz, b.w - hw);
            *(uint2*)&sBlo[so] = v;
        }
        __syncthreads();

#pragma unroll
        for (int ks = 0; ks < 4; ks++) {
            const int kb = ks * 16 + (lane & 3) * 2;
            // B fragments (hi+lo) for 4 n-tiles
            uint32_t bh[4][2], bl[4][2];
            const int nrow = wn * 32 + (lane >> 2);
#pragma unroll
            for (int nt = 0; nt < 4; nt++) {
                int nb = (nrow + nt * 8) * PITCH + kb;
                bh[nt][0] = *(uint32_t*)&sBhi[nb];
                bh[nt][1] = *(uint32_t*)&sBhi[nb + 8];
                bl[nt][0] = *(uint32_t*)&sBlo[nb];
                bl[nt][1] = *(uint32_t*)&sBlo[nb + 8];
            }
            const int arow = wm * 64 + (lane >> 2);
#pragma unroll
            for (int mt = 0; mt < 4; mt++) {
                int ab = (arow + mt * 16) * PITCH + kb;
                uint32_t ah[4], al[4];
                ah[0] = *(uint32_t*)&sAhi[ab];
                ah[1] = *(uint32_t*)&sAhi[ab + 8 * PITCH];
                ah[2] = *(uint32_t*)&sAhi[ab + 8];
                ah[3] = *(uint32_t*)&sAhi[ab + 8 * PITCH + 8];
                al[0] = *(uint32_t*)&sAlo[ab];
                al[1] = *(uint32_t*)&sAlo[ab + 8 * PITCH];
                al[2] = *(uint32_t*)&sAlo[ab + 8];
                al[3] = *(uint32_t*)&sAlo[ab + 8 * PITCH + 8];
#pragma unroll
                for (int nt = 0; nt < 4; nt++) {
                    mma16816(acc[mt][nt], ah, bh[nt]);
                    mma16816(acc[mt][nt], ah, bl[nt]);
                    mma16816(acc[mt][nt], al, bh[nt]);
                }
            }
        }
        __syncthreads();
    }

    // epilogue: warp writes its 64x32 region
    const int r0 = wm * 64 + (lane >> 2);
    const int c0 = wn * 32 + (lane & 3) * 2;
#pragma unroll
    for (int mt = 0; mt < 4; mt++) {
#pragma unroll
        for (int nt = 0; nt < 4; nt++) {
            int rr = r0 + mt * 16;
            int cc = c0 + nt * 8;
#pragma unroll
            for (int half = 0; half < 2; half++) {
                int r = rr + half * 8;
                float2 o;
                o.x = acc[mt][nt][half * 2 + 0] * scale;
                o.y = acc[mt][nt][half * 2 + 1] * scale;
                int gc = col0 + cc;
                if (bias) { o.x += bias[gc]; o.y += bias[gc + 1]; }
                if (mode == 1) {
                    if (gc + 0 >= PASTLEN && gc + 0 - PASTLEN > r) o.x = NEGF;
                    if (gc + 1 >= PASTLEN && gc + 1 - PASTLEN > r) o.y = NEGF;
                }
                *(float2*)(C + (size_t)r * ldc + cc) = o;
            }
        }
    }
}

// ---------------- RoPE Q ------------------------------------------------------
__global__ __launch_bounds__(256) void rope_q_kernel()
{
    int idx = blockIdx.x * 256 + threadIdx.x;
    int d = idx & 127;
    int t = (idx >> 7) & 127;
    int h = (idx >> 14) & 31;
    int b = idx >> 19;
    size_t base = ((size_t)(b * QLEN + t)) * HDIM + (size_t)h * DHEAD;
    int i = d & 63;
    float inv = 1.0f / powf(1.0e6f, (float)(2 * i) / 128.0f);
    float ang = (float)(PASTLEN + t) * inv;
    float s, c;
    sincosf(ang, &s, &c);
    float x  = g_qlin[base + d];
    float xo = g_qlin[base + ((d < 64) ? d + 64 : d - 64)];
    g_q[idx] = (d < 64) ? (x * c - xo * s) : (x * c + xo * s);
}

// ---------------- RoPE K new tokens -> g_kall ---------------------------------
__global__ __launch_bounds__(256) void rope_k_kernel()
{
    int idx = blockIdx.x * 256 + threadIdx.x;      // 4*8*128*128
    int d   = idx & 127;
    int t   = (idx >> 7) & 127;
    int kvh = (idx >> 14) & 7;
    int b   = idx >> 17;
    size_t base = ((size_t)(b * QLEN + t)) * KVDIM + (size_t)kvh * DHEAD;
    int i = d & 63;
    float inv = 1.0f / powf(1.0e6f, (float)(2 * i) / 128.0f);
    float ang = (float)(PASTLEN + t) * inv;
    float s, c;
    sincosf(ang, &s, &c);
    float x  = g_klin[base + d];
    float xo = g_klin[base + ((d < 64) ? d + 64 : d - 64)];
    g_kall[(((size_t)(b * NKVH + kvh)) * KVSEQ + PASTLEN + t) * DHEAD + d] =
        (d < 64) ? (x * c - xo * s) : (x * c + xo * s);
}

// ---------------- V new tokens -> g_vt (transposed) ---------------------------
__global__ __launch_bounds__(256) void v_scatter_kernel()
{
    int idx = blockIdx.x * 256 + threadIdx.x;      // 4*8*128*128, t inner
    int t   = idx & 127;
    int d   = (idx >> 7) & 127;
    int kvh = (idx >> 14) & 7;
    int b   = idx >> 17;
    g_vt[((size_t)(b * NKVH + kvh) * DHEAD + d) * KVSEQ + PASTLEN + t] =
        g_vlin[((size_t)(b * QLEN + t)) * KVDIM + kvh * DHEAD + d];
}

// ---------------- fp32 past copy ----------------------------------------------
__global__ __launch_bounds__(256) void past_copy_kernel(
    const float* __restrict__ kfp, const float* __restrict__ vfp)
{
    int idx = blockIdx.x * 256 + threadIdx.x;      // 32*128*128
    int d  = idx & 127;
    int r  = (idx >> 7) & 127;
    int bk = idx >> 14;
    size_t src = ((size_t)bk * RESLEN + r) * DHEAD + d;
    if (blockIdx.y == 0)
        g_kall[((size_t)bk * KVSEQ + NQK + r) * DHEAD + d] = kfp[src];
    else
        g_vt[((size_t)bk * DHEAD + d) * KVSEQ + NQK + r] = vfp[src];
}

// ---------------- dequant 2-bit K -> g_kall n-major ---------------------------
__global__ __launch_bounds__(256) void dequant_k_kernel(
    const int* __restrict__ kq, const float* __restrict__ ks,
    const float* __restrict__ km)
{
    int idx = blockIdx.x * 256 + threadIdx.x;      // 32*4096*128
    int d  = idx & 127;
    int n  = (idx >> 7) & 4095;
    int bk = idx >> 19;
    unsigned word = (unsigned)kq[((size_t)bk * DHEAD + d) * (NQK / 16) + (n >> 4)];
    float code = (float)((word >> ((n & 15) * 2)) & 3u);
    size_t sidx = ((size_t)bk * DHEAD + d) * (NQK / 64) + (n >> 6);
    g_kall[((size_t)bk * KVSEQ + n) * DHEAD + d] = code * ks[sidx] + km[sidx];
}

// ---------------- dequant 2-bit V -> g_vt d-major -----------------------------
__global__ __launch_bounds__(256) void dequant_v_kernel(
    const int* __restrict__ vq, const float* __restrict__ vs,
    const float* __restrict__ vm)
{
    int idx = blockIdx.x * 256 + threadIdx.x;      // 32*128*4096, n inner
    int n  = idx & 4095;
    int d  = (idx >> 12) & 127;
    int bk = idx >> 19;
    unsigned word = (unsigned)vq[((size_t)bk * NQK + n) * (DHEAD / 16) + (d >> 4)];
    float code = (float)((word >> ((d & 15) * 2)) & 3u);
    size_t sidx = ((size_t)bk * NQK + n) * (DHEAD / 64) + (d >> 6);
    g_vt[((size_t)bk * DHEAD + d) * KVSEQ + n] = code * vs[sidx] + vm[sidx];
}

// ---------------- row softmax over KVSEQ --------------------------------------
__global__ __launch_bounds__(256) void softmax_kernel()
{
    const int row = blockIdx.x;
    float* p = g_p + (size_t)row * KVSEQ;
    const int t = threadIdx.x;
    float v[17];
    float m = NEGF;
#pragma unroll
    for (int i = 0; i < 17; i++) {
        v[i] = p[t + i * 256];
        m = fmaxf(m, v[i]);
    }
    __shared__ float red[8];
#pragma unroll
    for (int o = 16; o > 0; o >>= 1) m = fmaxf(m, __shfl_xor_sync(0xffffffffu, m, o));
    if ((t & 31) == 0) red[t >> 5] = m;
    __syncthreads();
    float bm = red[0];
#pragma unroll
    for (int w = 1; w < 8; w++) bm = fmaxf(bm, red[w]);
    __syncthreads();
    float s = 0.f;
#pragma unroll
    for (int i = 0; i < 17; i++) {
        v[i] = expf(v[i] - bm);
        s += v[i];
    }
#pragma unroll
    for (int o = 16; o > 0; o >>= 1) s += __shfl_xor_sync(0xffffffffu, s, o);
    if ((t & 31) == 0) red[t >> 5] = s;
    __syncthreads();
    float tot = 0.f;
#pragma unroll
    for (int w = 0; w < 8; w++) tot += red[w];
    float inv = 1.0f / tot;
#pragma unroll
    for (int i = 0; i < 17; i++) p[t + i * 256] = v[i] * inv;
}

// ---------------- host launch --------------------------------------------------
extern "C" void kernel_launch(void* const* d_in, const int* in_sizes, int n_in,
                              void* d_out, int out_size)
{
    (void)in_sizes; (void)n_in; (void)out_size;
    const float* hs  = (const float*)d_in[0];
    const float* qw  = (const float*)d_in[1];
    const float* qb  = (const float*)d_in[2];
    const float* kw  = (const float*)d_in[3];
    const float* kb  = (const float*)d_in[4];
    const float* vw  = (const float*)d_in[5];
    const float* vb  = (const float*)d_in[6];
    const float* ow  = (const float*)d_in[7];
    const int*   kqt = (const int*)  d_in[8];
    const float* kst = (const float*)d_in[9];
    const float* kmt = (const float*)d_in[10];
    const float* kfp = (const float*)d_in[11];
    const int*   vq  = (const int*)  d_in[12];
    const float* vs  = (const float*)d_in[13];
    const float* vm  = (const float*)d_in[14];
    const float* vfp = (const float*)d_in[15];
    float* out = (float*)d_out;

    float *qlin, *klin, *vlin, *ao;
    cudaGetSymbolAddress((void**)&qlin, g_qlin);
    cudaGetSymbolAddress((void**)&klin, g_klin);
    cudaGetSymbolAddress((void**)&vlin, g_vlin);
    cudaGetSymbolAddress((void**)&ao,   g_ao);

    cudaFuncSetAttribute(gemm_mma, cudaFuncAttributeMaxDynamicSharedMemorySize, S_TOTAL);

    dim3 blk(256);
    const float isq = 0.08838834764831845f;   // 1/sqrt(128)

    // QKV projections (+bias)
    gemm_mma<<<dim3(32, 4), blk, S_TOTAL>>>(hs, qw, qb, qlin, HDIM, HDIM, HDIM,  HDIM, 0, 1.f);
    gemm_mma<<<dim3(8,  4), blk, S_TOTAL>>>(hs, kw, kb, klin, HDIM, HDIM, KVDIM, HDIM, 0, 1.f);
    gemm_mma<<<dim3(8,  4), blk, S_TOTAL>>>(hs, vw, vb, vlin, HDIM, HDIM, KVDIM, HDIM, 0, 1.f);

    // RoPE + cache assembly
    rope_q_kernel<<<(TOK * HDIM) / 256, blk>>>();
    rope_k_kernel<<<(TOK * KVDIM) / 256, blk>>>();
    v_scatter_kernel<<<(TOK * KVDIM) / 256, blk>>>();
    past_copy_kernel<<<dim3((32 * RESLEN * DHEAD) / 256, 2), blk>>>(kfp, vfp);
    dequant_k_kernel<<<(32 * NQK * DHEAD) / 256, blk>>>(kqt, kst, kmt);
    dequant_v_kernel<<<(32 * NQK * DHEAD) / 256, blk>>>(vq, vs, vm);

    // attention: scores (scale + causal mask fused), softmax, PV
    gemm_mma<<<dim3(KVSEQ / 128, BATCH * NHEAD), blk, S_TOTAL>>>(
        nullptr, nullptr, nullptr, nullptr, DHEAD, DHEAD, KVSEQ, DHEAD, 1, isq);
    softmax_kernel<<<BATCH * NHEAD * QLEN, blk>>>();
    gemm_mma<<<dim3(1, BATCH * NHEAD), blk, S_TOTAL>>>(
        nullptr, nullptr, nullptr, nullptr, KVSEQ, KVSEQ, HDIM, KVSEQ, 2, 1.f);

    // output projection
    gemm_mma<<<dim3(32, 4), blk, S_TOTAL>>>(ao, ow, nullptr, out, HDIM, HDIM, HDIM, HDIM, 0, 1.f);
}

// round 8
// speedup vs baseline: 2.4686x; 1.2899x over previous
#include <cuda_runtime.h>
#include <cuda_bf16.h>
#include <math.h>
#include <float.h>
#include <stdint.h>

// ---------------- problem constants ----------------
#define BATCH   4
#define QLEN    128
#define HDIM    4096
#define NHEAD   32
#define NKVH    8
#define DHEAD   128
#define KVDIM   1024
#define TOK     512
#define NQK     4096
#define RESLEN  128
#define KVSEQ   4352
#define PASTLEN 4224
#define NBLK    68            // KVSEQ / 64
#define NEGF    (-3.402823466e38f)

// ---------------- scratch ----------------
__device__ float g_qlin[TOK * HDIM];
__device__ float g_klin[TOK * KVDIM];
__device__ float g_vlin[TOK * KVDIM];
__device__ float g_q   [BATCH * NHEAD * QLEN * DHEAD];         // [bh][q][d] fp32

// pre-split bf16 hi/lo operand arrays
__device__ __nv_bfloat16 g_hshi[TOK * HDIM],  g_hslo[TOK * HDIM];
__device__ __nv_bfloat16 g_qwhi[HDIM * HDIM], g_qwlo[HDIM * HDIM];
__device__ __nv_bfloat16 g_kwhi[KVDIM * HDIM], g_kwlo[KVDIM * HDIM];
__device__ __nv_bfloat16 g_vwhi[KVDIM * HDIM], g_vwlo[KVDIM * HDIM];
__device__ __nv_bfloat16 g_owhi[HDIM * HDIM], g_owlo[HDIM * HDIM];
__device__ __nv_bfloat16 g_khi [BATCH * NKVH * KVSEQ * DHEAD]; // [bk][n][d]
__device__ __nv_bfloat16 g_klo [BATCH * NKVH * KVSEQ * DHEAD];
__device__ __nv_bfloat16 g_vthi[BATCH * NKVH * DHEAD * KVSEQ]; // [bk][d][n]
__device__ __nv_bfloat16 g_vtlo[BATCH * NKVH * DHEAD * KVSEQ];
__device__ __nv_bfloat16 g_aohi[TOK * HDIM],  g_aolo[TOK * HDIM];

// ---------------- helpers ----------------
__device__ __forceinline__ void mma16816(float* c, const uint32_t* a, const uint32_t* b) {
    asm volatile(
        "mma.sync.aligned.m16n8k16.row.col.f32.bf16.bf16.f32 "
        "{%0,%1,%2,%3}, {%4,%5,%6,%7}, {%8,%9}, {%0,%1,%2,%3};"
        : "+f"(c[0]), "+f"(c[1]), "+f"(c[2]), "+f"(c[3])
        : "r"(a[0]), "r"(a[1]), "r"(a[2]), "r"(a[3]), "r"(b[0]), "r"(b[1]));
}
__device__ __forceinline__ uint32_t packb(__nv_bfloat16 a, __nv_bfloat16 b) {
    __nv_bfloat162 p(a, b);
    return *(uint32_t*)&p;
}
__device__ __forceinline__ void split2(float x0, float x1, uint32_t& hi, uint32_t& lo) {
    __nv_bfloat16 h0 = __float2bfloat16(x0), h1 = __float2bfloat16(x1);
    hi = packb(h0, h1);
    lo = packb(__float2bfloat16(x0 - __bfloat162float(h0)),
               __float2bfloat16(x1 - __bfloat162float(h1)));
}

// ---------------- fp32 -> bf16 hi/lo splitter ---------------------------------
__global__ __launch_bounds__(256) void split_f32(
    const float* __restrict__ in, __nv_bfloat16* __restrict__ hi,
    __nv_bfloat16* __restrict__ lo)
{
    int i = (blockIdx.x * 256 + threadIdx.x) * 4;
    float4 v = *(const float4*)(in + i);
    uint32_t h0, l0, h1, l1;
    split2(v.x, v.y, h0, l0);
    split2(v.z, v.w, h1, l1);
    uint2 H; H.x = h0; H.y = h1;
    uint2 L; L.x = l0; L.y = l1;
    *(uint2*)(hi + i) = H;
    *(uint2*)(lo + i) = L;
}

// ---------------- pre-split bf16 HMMA GEMM ------------------------------------
// C[m][n] = sum_k A[m][k]*B[n][k] (+bias), all operands pre-split bf16 hi/lo.
#define PITCH 72
#define TILE_ELEMS (128 * PITCH)
#define S_GEMM (4 * TILE_ELEMS * 2)   // 73728 B

__global__ __launch_bounds__(256) void gemm_bf16(
    const __nv_bfloat16* __restrict__ Ahi, const __nv_bfloat16* __restrict__ Alo,
    const __nv_bfloat16* __restrict__ Bhi, const __nv_bfloat16* __restrict__ Blo,
    const float* __restrict__ bias, float* __restrict__ C,
    int lda, int ldb, int ldc, int K)
{
    extern __shared__ __nv_bfloat16 sm[];
    __nv_bfloat16* sAhi = sm;
    __nv_bfloat16* sAlo = sm + TILE_ELEMS;
    __nv_bfloat16* sBhi = sm + 2 * TILE_ELEMS;
    __nv_bfloat16* sBlo = sm + 3 * TILE_ELEMS;

    const int tid  = threadIdx.x;
    const int lane = tid & 31;
    const int wid  = tid >> 5;
    const int wm   = wid >> 2;
    const int wn   = wid & 3;

    const size_t arow0 = (size_t)(blockIdx.y * 128);
    const size_t brow0 = (size_t)(blockIdx.x * 128);
    float* Cp = C + arow0 * ldc + brow0;

    float acc[4][4][4];
#pragma unroll
    for (int mt = 0; mt < 4; mt++)
#pragma unroll
        for (int nt = 0; nt < 4; nt++)
#pragma unroll
            for (int i = 0; i < 4; i++) acc[mt][nt][i] = 0.f;

    const int nchunks = K >> 6;
    for (int ch = 0; ch < nchunks; ch++) {
        const int k0 = ch << 6;
#pragma unroll
        for (int i = 0; i < 4; i++) {
            int u = i * 256 + tid;          // 0..1023 uint4 slots
            int r = u >> 3, kp = (u & 7) * 8;
            size_t aoff = (arow0 + r) * lda + k0 + kp;
            size_t boff = (brow0 + r) * ldb + k0 + kp;
            int so = r * PITCH + kp;
            *(uint4*)&sAhi[so] = *(const uint4*)(Ahi + aoff);
            *(uint4*)&sAlo[so] = *(const uint4*)(Alo + aoff);
            *(uint4*)&sBhi[so] = *(const uint4*)(Bhi + boff);
            *(uint4*)&sBlo[so] = *(const uint4*)(Blo + boff);
        }
        __syncthreads();

#pragma unroll
        for (int ks = 0; ks < 4; ks++) {
            const int kb = ks * 16 + (lane & 3) * 2;
            uint32_t bh[4][2], bl[4][2];
            const int nrow = wn * 32 + (lane >> 2);
#pragma unroll
            for (int nt = 0; nt < 4; nt++) {
                int nb = (nrow + nt * 8) * PITCH + kb;
                bh[nt][0] = *(uint32_t*)&sBhi[nb];
                bh[nt][1] = *(uint32_t*)&sBhi[nb + 8];
                bl[nt][0] = *(uint32_t*)&sBlo[nb];
                bl[nt][1] = *(uint32_t*)&sBlo[nb + 8];
            }
            const int arow = wm * 64 + (lane >> 2);
#pragma unroll
            for (int mt = 0; mt < 4; mt++) {
                int ab = (arow + mt * 16) * PITCH + kb;
                uint32_t ah[4], al[4];
                ah[0] = *(uint32_t*)&sAhi[ab];
                ah[1] = *(uint32_t*)&sAhi[ab + 8 * PITCH];
                ah[2] = *(uint32_t*)&sAhi[ab + 8];
                ah[3] = *(uint32_t*)&sAhi[ab + 8 * PITCH + 8];
                al[0] = *(uint32_t*)&sAlo[ab];
                al[1] = *(uint32_t*)&sAlo[ab + 8 * PITCH];
                al[2] = *(uint32_t*)&sAlo[ab + 8];
                al[3] = *(uint32_t*)&sAlo[ab + 8 * PITCH + 8];
#pragma unroll
                for (int nt = 0; nt < 4; nt++) {
                    mma16816(acc[mt][nt], ah, bh[nt]);
                    mma16816(acc[mt][nt], ah, bl[nt]);
                    mma16816(acc[mt][nt], al, bh[nt]);
                }
            }
        }
        __syncthreads();
    }

    const int r0 = wm * 64 + (lane >> 2);
    const int c0 = wn * 32 + (lane & 3) * 2;
#pragma unroll
    for (int mt = 0; mt < 4; mt++) {
#pragma unroll
        for (int nt = 0; nt < 4; nt++) {
            int cc = c0 + nt * 8;
#pragma unroll
            for (int half = 0; half < 2; half++) {
                int r = r0 + mt * 16 + half * 8;
                float2 o;
                o.x = acc[mt][nt][half * 2 + 0];
                o.y = acc[mt][nt][half * 2 + 1];
                if (bias) {
                    o.x += bias[brow0 + cc];
                    o.y += bias[brow0 + cc + 1];
                }
                *(float2*)(Cp + (size_t)r * ldc + cc) = o;
            }
        }
    }
}

// ---------------- fused flash attention ---------------------------------------
// grid = 128 (bh). 8 warps x 16 q-rows. Bc = 64, 68 kv blocks.
#define FK_PITCH 136
#define FV_PITCH 72
#define S_FLASH ((64 * FK_PITCH * 2 + 128 * FV_PITCH * 2) * 2)   // 71680 B

__global__ __launch_bounds__(256, 1) void flash_attn()
{
    extern __shared__ __nv_bfloat16 fsm[];
    __nv_bfloat16* sKhi = fsm;
    __nv_bfloat16* sKlo = fsm + 64 * FK_PITCH;
    __nv_bfloat16* sVhi = fsm + 2 * 64 * FK_PITCH;
    __nv_bfloat16* sVlo = sVhi + 128 * FV_PITCH;

    const int bh = blockIdx.x;
    const int b = bh >> 5, h = bh & 31, kvh = h >> 2;
    const int bk = b * NKVH + kvh;
    const int tid = threadIdx.x, lane = tid & 31, w = tid >> 5;
    const int rq = w * 16 + (lane >> 2);       // q row for c0/c1 (c2/c3 = +8)
    const int q2 = (lane & 3) * 2;
    const float isq = 0.08838834764831845f;

    // Q fragments (split once, register-resident)
    const float* Q = g_q + (size_t)bh * QLEN * DHEAD;
    uint32_t qhi[8][4], qlo[8][4];
#pragma unroll
    for (int kk = 0; kk < 8; kk++) {
#pragma unroll
        for (int f = 0; f < 4; f++) {
            int rr = rq + ((f & 1) ? 8 : 0);
            int kc = kk * 16 + ((f & 2) ? 8 : 0) + q2;
            split2(Q[rr * DHEAD + kc], Q[rr * DHEAD + kc + 1], qhi[kk][f], qlo[kk][f]);
        }
    }

    const __nv_bfloat16* Khi = g_khi + (size_t)bk * KVSEQ * DHEAD;
    const __nv_bfloat16* Klo = g_klo + (size_t)bk * KVSEQ * DHEAD;
    const __nv_bfloat16* Vhi = g_vthi + (size_t)bk * DHEAD * KVSEQ;
    const __nv_bfloat16* Vlo = g_vtlo + (size_t)bk * DHEAD * KVSEQ;

    float m0 = NEGF, m1 = NEGF, l0 = 0.f, l1 = 0.f;
    float oacc[16][4];
#pragma unroll
    for (int td = 0; td < 16; td++)
#pragma unroll
        for (int i = 0; i < 4; i++) oacc[td][i] = 0.f;

    for (int j = 0; j < NBLK; j++) {
        // stage K block (64 kv-rows x 128 d) and V^T block (128 d x 64 kv)
#pragma unroll
        for (int i = 0; i < 4; i++) {
            int u = i * 256 + tid;
            int n = u >> 4, kp = (u & 15) * 8;
            size_t go = (size_t)(j * 64 + n) * DHEAD + kp;
            *(uint4*)&sKhi[n * FK_PITCH + kp] = *(const uint4*)(Khi + go);
            *(uint4*)&sKlo[n * FK_PITCH + kp] = *(const uint4*)(Klo + go);
            int d = u >> 3, vp = (u & 7) * 8;
            size_t gv = (size_t)d * KVSEQ + j * 64 + vp;
            *(uint4*)&sVhi[d * FV_PITCH + vp] = *(const uint4*)(Vhi + gv);
            *(uint4*)&sVlo[d * FV_PITCH + vp] = *(const uint4*)(Vlo + gv);
        }
        __syncthreads();

        // S = Q K^T  (16 x 64 per warp)
        float sacc[8][4];
#pragma unroll
        for (int nt = 0; nt < 8; nt++)
#pragma unroll
            for (int i = 0; i < 4; i++) sacc[nt][i] = 0.f;

#pragma unroll
        for (int kk = 0; kk < 8; kk++) {
            const int kb = kk * 16 + q2;
#pragma unroll
            for (int nt = 0; nt < 8; nt++) {
                int nb = (nt * 8 + (lane >> 2)) * FK_PITCH + kb;
                uint32_t bhf[2], blf[2];
                bhf[0] = *(uint32_t*)&sKhi[nb];
                bhf[1] = *(uint32_t*)&sKhi[nb + 8];
                blf[0] = *(uint32_t*)&sKlo[nb];
                blf[1] = *(uint32_t*)&sKlo[nb + 8];
                mma16816(sacc[nt], qhi[kk], bhf);
                mma16816(sacc[nt], qhi[kk], blf);
                mma16816(sacc[nt], qlo[kk], bhf);
            }
        }

        // scale + causal mask (only last two blocks touch new tokens)
#pragma unroll
        for (int nt = 0; nt < 8; nt++)
#pragma unroll
            for (int i = 0; i < 4; i++) sacc[nt][i] *= isq;
        if (j >= 66) {
            int jc = j * 64 - PASTLEN;
#pragma unroll
            for (int nt = 0; nt < 8; nt++) {
                int c = jc + nt * 8 + q2;
                if (c     > rq)     sacc[nt][0] = NEGF;
                if (c + 1 > rq)     sacc[nt][1] = NEGF;
                if (c     > rq + 8) sacc[nt][2] = NEGF;
                if (c + 1 > rq + 8) sacc[nt][3] = NEGF;
            }
        }

        // row max (quad reduce)
        float mx0 = NEGF, mx1 = NEGF;
#pragma unroll
        for (int nt = 0; nt < 8; nt++) {
            mx0 = fmaxf(mx0, fmaxf(sacc[nt][0], sacc[nt][1]));
            mx1 = fmaxf(mx1, fmaxf(sacc[nt][2], sacc[nt][3]));
        }
        mx0 = fmaxf(mx0, __shfl_xor_sync(0xffffffffu, mx0, 1));
        mx0 = fmaxf(mx0, __shfl_xor_sync(0xffffffffu, mx0, 2));
        mx1 = fmaxf(mx1, __shfl_xor_sync(0xffffffffu, mx1, 1));
        mx1 = fmaxf(mx1, __shfl_xor_sync(0xffffffffu, mx1, 2));

        float mn0 = fmaxf(m0, mx0), mn1 = fmaxf(m1, mx1);
        float a0 = __expf(m0 - mn0), a1 = __expf(m1 - mn1);

        // P = exp(S - m) + row sums
        float rs0 = 0.f, rs1 = 0.f;
#pragma unroll
        for (int nt = 0; nt < 8; nt++) {
            sacc[nt][0] = __expf(sacc[nt][0] - mn0);
            sacc[nt][1] = __expf(sacc[nt][1] - mn0);
            sacc[nt][2] = __expf(sacc[nt][2] - mn1);
            sacc[nt][3] = __expf(sacc[nt][3] - mn1);
            rs0 += sacc[nt][0] + sacc[nt][1];
            rs1 += sacc[nt][2] + sacc[nt][3];
        }
        rs0 += __shfl_xor_sync(0xffffffffu, rs0, 1);
        rs0 += __shfl_xor_sync(0xffffffffu, rs0, 2);
        rs1 += __shfl_xor_sync(0xffffffffu, rs1, 1);
        rs1 += __shfl_xor_sync(0xffffffffu, rs1, 2);
        l0 = l0 * a0 + rs0;
        l1 = l1 * a1 + rs1;
        m0 = mn0; m1 = mn1;

        // rescale O
#pragma unroll
        for (int td = 0; td < 16; td++) {
            oacc[td][0] *= a0; oacc[td][1] *= a0;
            oacc[td][2] *= a1; oacc[td][3] *= a1;
        }

        // O += P V   (P lives in sacc; C-frag == A-frag layout)
#pragma unroll
        for (int kk2 = 0; kk2 < 4; kk2++) {
            uint32_t phi[4], plo[4];
            split2(sacc[2 * kk2][0],     sacc[2 * kk2][1],     phi[0], plo[0]);
            split2(sacc[2 * kk2][2],     sacc[2 * kk2][3],     phi[1], plo[1]);
            split2(sacc[2 * kk2 + 1][0], sacc[2 * kk2 + 1][1], phi[2], plo[2]);
            split2(sacc[2 * kk2 + 1][2], sacc[2 * kk2 + 1][3], phi[3], plo[3]);
            const int kb = kk2 * 16 + q2;
#pragma unroll
            for (int td = 0; td < 16; td++) {
                int vb = (td * 8 + (lane >> 2)) * FV_PITCH + kb;
                uint32_t vbh[2], vbl[2];
                vbh[0] = *(uint32_t*)&sVhi[vb];
                vbh[1] = *(uint32_t*)&sVhi[vb + 8];
                vbl[0] = *(uint32_t*)&sVlo[vb];
                vbl[1] = *(uint32_t*)&sVlo[vb + 8];
                mma16816(oacc[td], phi, vbh);
                mma16816(oacc[td], phi, vbl);
                mma16816(oacc[td], plo, vbh);
            }
        }
        __syncthreads();
    }

    // epilogue: O /= l, write split bf16 to g_ao{hi,lo}
    float inv0 = 1.f / l0, inv1 = 1.f / l1;
#pragma unroll
    for (int td = 0; td < 16; td++) {
        int cd = h * DHEAD + td * 8 + q2;
        {
            float x0 = oacc[td][0] * inv0, x1 = oacc[td][1] * inv0;
            uint32_t hi, lo;
            split2(x0, x1, hi, lo);
            size_t o = (size_t)(b * QLEN + rq) * HDIM + cd;
            *(uint32_t*)&g_aohi[o] = hi;
            *(uint32_t*)&g_aolo[o] = lo;
        }
        {
            float x0 = oacc[td][2] * inv1, x1 = oacc[td][3] * inv1;
            uint32_t hi, lo;
            split2(x0, x1, hi, lo);
            size_t o = (size_t)(b * QLEN + rq + 8) * HDIM + cd;
            *(uint32_t*)&g_aohi[o] = hi;
            *(uint32_t*)&g_aolo[o] = lo;
        }
    }
}

// ---------------- RoPE Q ------------------------------------------------------
__global__ __launch_bounds__(256) void rope_q_kernel()
{
    int idx = blockIdx.x * 256 + threadIdx.x;
    int d = idx & 127;
    int t = (idx >> 7) & 127;
    int h = (idx >> 14) & 31;
    int b = idx >> 19;
    size_t base = ((size_t)(b * QLEN + t)) * HDIM + (size_t)h * DHEAD;
    int i = d & 63;
    float inv = 1.0f / powf(1.0e6f, (float)(2 * i) / 128.0f);
    float ang = (float)(PASTLEN + t) * inv;
    float s, c;
    sincosf(ang, &s, &c);
    float x  = g_qlin[base + d];
    float xo = g_qlin[base + ((d < 64) ? d + 64 : d - 64)];
    g_q[idx] = (d < 64) ? (x * c - xo * s) : (x * c + xo * s);
}

// ---------------- RoPE K new tokens -> split K cache --------------------------
__global__ __launch_bounds__(256) void rope_k_kernel()
{
    int idx = blockIdx.x * 256 + threadIdx.x;      // 4*8*128*128
    int d   = idx & 127;
    int t   = (idx >> 7) & 127;
    int kvh = (idx >> 14) & 7;
    int b   = idx >> 17;
    size_t base = ((size_t)(b * QLEN + t)) * KVDIM + (size_t)kvh * DHEAD;
    int i = d & 63;
    float inv = 1.0f / powf(1.0e6f, (float)(2 * i) / 128.0f);
    float ang = (float)(PASTLEN + t) * inv;
    float s, c;
    sincosf(ang, &s, &c);
    float x  = g_klin[base + d];
    float xo = g_klin[base + ((d < 64) ? d + 64 : d - 64)];
    float v  = (d < 64) ? (x * c - xo * s) : (x * c + xo * s);
    size_t o = (((size_t)(b * NKVH + kvh)) * KVSEQ + PASTLEN + t) * DHEAD + d;
    __nv_bfloat16 hi = __float2bfloat16(v);
    g_khi[o] = hi;
    g_klo[o] = __float2bfloat16(v - __bfloat162float(hi));
}

// ---------------- V new tokens -> split V^T cache -----------------------------
__global__ __launch_bounds__(256) void v_scatter_kernel()
{
    int idx = blockIdx.x * 256 + threadIdx.x;      // t inner
    int t   = idx & 127;
    int d   = (idx >> 7) & 127;
    int kvh = (idx >> 14) & 7;
    int b   = idx >> 17;
    float v = g_vlin[((size_t)(b * QLEN + t)) * KVDIM + kvh * DHEAD + d];
    size_t o = ((size_t)(b * NKVH + kvh) * DHEAD + d) * KVSEQ + PASTLEN + t;
    __nv_bfloat16 hi = __float2bfloat16(v);
    g_vthi[o] = hi;
    g_vtlo[o] = __float2bfloat16(v - __bfloat162float(hi));
}

// ---------------- fp32 past copy (split) --------------------------------------
__global__ __launch_bounds__(256) void past_copy_kernel(
    const float* __restrict__ kfp, const float* __restrict__ vfp)
{
    int idx = blockIdx.x * 256 + threadIdx.x;      // 32*128*128
    int d  = idx & 127;
    int r  = (idx >> 7) & 127;
    int bk = idx >> 14;
    size_t src = ((size_t)bk * RESLEN + r) * DHEAD + d;
    if (blockIdx.y == 0) {
        float v = kfp[src];
        size_t o = ((size_t)bk * KVSEQ + NQK + r) * DHEAD + d;
        __nv_bfloat16 hi = __float2bfloat16(v);
        g_khi[o] = hi;
        g_klo[o] = __float2bfloat16(v - __bfloat162float(hi));
    } else {
        float v = vfp[src];
        size_t o = ((size_t)bk * DHEAD + d) * KVSEQ + NQK + r;
        __nv_bfloat16 hi = __float2bfloat16(v);
        g_vthi[o] = hi;
        g_vtlo[o] = __float2bfloat16(v - __bfloat162float(hi));
    }
}

// ---------------- dequant 2-bit K -> split K cache ----------------------------
__global__ __launch_bounds__(256) void dequant_k_kernel(
    const int* __restrict__ kq, const float* __restrict__ ks,
    const float* __restrict__ km)
{
    int idx = blockIdx.x * 256 + threadIdx.x;      // 32*4096*128, d inner
    int d  = idx & 127;
    int n  = (idx >> 7) & 4095;
    int bk = idx >> 19;
    unsigned word = (unsigned)kq[((size_t)bk * DHEAD + d) * (NQK / 16) + (n >> 4)];
    float code = (float)((word >> ((n & 15) * 2)) & 3u);
    size_t sidx = ((size_t)bk * DHEAD + d) * (NQK / 64) + (n >> 6);
    float v = code * ks[sidx] + km[sidx];
    size_t o = ((size_t)bk * KVSEQ + n) * DHEAD + d;
    __nv_bfloat16 hi = __float2bfloat16(v);
    g_khi[o] = hi;
    g_klo[o] = __float2bfloat16(v - __bfloat162float(hi));
}

// ---------------- dequant 2-bit V -> split V^T cache --------------------------
__global__ __launch_bounds__(256) void dequant_v_kernel(
    const int* __restrict__ vq, const float* __restrict__ vs,
    const float* __restrict__ vm)
{
    int idx = blockIdx.x * 256 + threadIdx.x;      // 32*128*4096, n inner
    int n  = idx & 4095;
    int d  = (idx >> 12) & 127;
    int bk = idx >> 19;
    unsigned word = (unsigned)vq[((size_t)bk * NQK + n) * (DHEAD / 16) + (d >> 4)];
    float code = (float)((word >> ((d & 15) * 2)) & 3u);
    size_t sidx = ((size_t)bk * NQK + n) * (DHEAD / 64) + (d >> 6);
    float v = code * vs[sidx] + vm[sidx];
    size_t o = ((size_t)bk * DHEAD + d) * KVSEQ + n;
    __nv_bfloat16 hi = __float2bfloat16(v);
    g_vthi[o] = hi;
    g_vtlo[o] = __float2bfloat16(v - __bfloat162float(hi));
}

// ---------------- host launch --------------------------------------------------
extern "C" void kernel_launch(void* const* d_in, const int* in_sizes, int n_in,
                              void* d_out, int out_size)
{
    (void)in_sizes; (void)n_in; (void)out_size;
    const float* hs  = (const float*)d_in[0];
    const float* qw  = (const float*)d_in[1];
    const float* qb  = (const float*)d_in[2];
    const float* kw  = (const float*)d_in[3];
    const float* kb  = (const float*)d_in[4];
    const float* vw  = (const float*)d_in[5];
    const float* vb  = (const float*)d_in[6];
    const float* ow  = (const float*)d_in[7];
    const int*   kqt = (const int*)  d_in[8];
    const float* kst = (const float*)d_in[9];
    const float* kmt = (const float*)d_in[10];
    const float* kfp = (const float*)d_in[11];
    const int*   vq  = (const int*)  d_in[12];
    const float* vs  = (const float*)d_in[13];
    const float* vm  = (const float*)d_in[14];
    const float* vfp = (const float*)d_in[15];
    float* out = (float*)d_out;

    float *qlin, *klin, *vlin;
    __nv_bfloat16 *hshi, *hslo, *qwhi, *qwlo, *kwhi, *kwlo, *vwhi, *vwlo;
    __nv_bfloat16 *owhi, *owlo, *aohi, *aolo;
    cudaGetSymbolAddress((void**)&qlin, g_qlin);
    cudaGetSymbolAddress((void**)&klin, g_klin);
    cudaGetSymbolAddress((void**)&vlin, g_vlin);
    cudaGetSymbolAddress((void**)&hshi, g_hshi);
    cudaGetSymbolAddress((void**)&hslo, g_hslo);
    cudaGetSymbolAddress((void**)&qwhi, g_qwhi);
    cudaGetSymbolAddress((void**)&qwlo, g_qwlo);
    cudaGetSymbolAddress((void**)&kwhi, g_kwhi);
    cudaGetSymbolAddress((void**)&kwlo, g_kwlo);
    cudaGetSymbolAddress((void**)&vwhi, g_vwhi);
    cudaGetSymbolAddress((void**)&vwlo, g_vwlo);
    cudaGetSymbolAddress((void**)&owhi, g_owhi);
    cudaGetSymbolAddress((void**)&owlo, g_owlo);
    cudaGetSymbolAddress((void**)&aohi, g_aohi);
    cudaGetSymbolAddress((void**)&aolo, g_aolo);

    cudaFuncSetAttribute(gemm_bf16, cudaFuncAttributeMaxDynamicSharedMemorySize, S_GEMM);
    cudaFuncSetAttribute(flash_attn, cudaFuncAttributeMaxDynamicSharedMemorySize, S_FLASH);

    dim3 blk(256);

    // operand pre-split
    split_f32<<<(TOK * HDIM) / 1024, blk>>>(hs, hshi, hslo);
    split_f32<<<(HDIM * HDIM) / 1024, blk>>>(qw, qwhi, qwlo);
    split_f32<<<(KVDIM * HDIM) / 1024, blk>>>(kw, kwhi, kwlo);
    split_f32<<<(KVDIM * HDIM) / 1024, blk>>>(vw, vwhi, vwlo);
    split_f32<<<(HDIM * HDIM) / 1024, blk>>>(ow, owhi, owlo);

    // QKV projections
    gemm_bf16<<<dim3(32, 4), blk, S_GEMM>>>(hshi, hslo, qwhi, qwlo, qb, qlin, HDIM, HDIM, HDIM,  HDIM);
    gemm_bf16<<<dim3(8,  4), blk, S_GEMM>>>(hshi, hslo, kwhi, kwlo, kb, klin, HDIM, HDIM, KVDIM, HDIM);
    gemm_bf16<<<dim3(8,  4), blk, S_GEMM>>>(hshi, hslo, vwhi, vwlo, vb, vlin, HDIM, HDIM, KVDIM, HDIM);

    // RoPE + cache assembly (split bf16 caches)
    rope_q_kernel<<<(TOK * HDIM) / 256, blk>>>();
    rope_k_kernel<<<(TOK * KVDIM) / 256, blk>>>();
    v_scatter_kernel<<<(TOK * KVDIM) / 256, blk>>>();
    past_copy_kernel<<<dim3((32 * RESLEN * DHEAD) / 256, 2), blk>>>(kfp, vfp);
    dequant_k_kernel<<<(32 * NQK * DHEAD) / 256, blk>>>(kqt, kst, kmt);
    dequant_v_kernel<<<(32 * NQK * DHEAD) / 256, blk>>>(vq, vs, vm);

    // fused attention (scores + softmax + PV)
    flash_attn<<<BATCH * NHEAD, blk, S_FLASH>>>();

    // output projection
    gemm_bf16<<<dim3(32, 4), blk, S_GEMM>>>(aohi, aolo, owhi, owlo, nullptr, out, HDIM, HDIM, HDIM, HDIM);
}

// round 9
// speedup vs baseline: 3.6156x; 1.4647x over previous
#include <cuda_runtime.h>
#include <cuda_bf16.h>
#include <math.h>
#include <float.h>
#include <stdint.h>

// ---------------- problem constants ----------------
#define BATCH   4
#define QLEN    128
#define HDIM    4096
#define NHEAD   32
#define NKVH    8
#define DHEAD   128
#define KVDIM   1024
#define TOK     512
#define NQK     4096
#define RESLEN  128
#define KVSEQ   4352
#define PASTLEN 4224
#define NBLK    68            // KVSEQ / 64
#define NEGF    (-3.402823466e38f)

// ---------------- scratch ----------------
__device__ float g_qlin[TOK * HDIM];
__device__ float g_klin[TOK * KVDIM];
__device__ float g_vlin[TOK * KVDIM];
__device__ float g_q   [BATCH * NHEAD * QLEN * DHEAD];         // [bh][q][d] fp32

__device__ __nv_bfloat16 g_hshi[TOK * HDIM],  g_hslo[TOK * HDIM];
__device__ __nv_bfloat16 g_qwhi[HDIM * HDIM], g_qwlo[HDIM * HDIM];
__device__ __nv_bfloat16 g_kwhi[KVDIM * HDIM], g_kwlo[KVDIM * HDIM];
__device__ __nv_bfloat16 g_vwhi[KVDIM * HDIM], g_vwlo[KVDIM * HDIM];
__device__ __nv_bfloat16 g_owhi[HDIM * HDIM], g_owlo[HDIM * HDIM];
__device__ __nv_bfloat16 g_khi [BATCH * NKVH * KVSEQ * DHEAD]; // [bk][n][d]
__device__ __nv_bfloat16 g_klo [BATCH * NKVH * KVSEQ * DHEAD];
__device__ __nv_bfloat16 g_vthi[BATCH * NKVH * DHEAD * KVSEQ]; // [bk][d][n]
__device__ __nv_bfloat16 g_vtlo[BATCH * NKVH * DHEAD * KVSEQ];
__device__ __nv_bfloat16 g_aohi[TOK * HDIM],  g_aolo[TOK * HDIM];

// ---------------- helpers ----------------
__device__ __forceinline__ void mma16816(float* c, const uint32_t* a, const uint32_t* b) {
    asm volatile(
        "mma.sync.aligned.m16n8k16.row.col.f32.bf16.bf16.f32 "
        "{%0,%1,%2,%3}, {%4,%5,%6,%7}, {%8,%9}, {%0,%1,%2,%3};"
        : "+f"(c[0]), "+f"(c[1]), "+f"(c[2]), "+f"(c[3])
        : "r"(a[0]), "r"(a[1]), "r"(a[2]), "r"(a[3]), "r"(b[0]), "r"(b[1]));
}
__device__ __forceinline__ uint32_t packb(__nv_bfloat16 a, __nv_bfloat16 b) {
    __nv_bfloat162 p(a, b);
    return *(uint32_t*)&p;
}
__device__ __forceinline__ void split2(float x0, float x1, uint32_t& hi, uint32_t& lo) {
    __nv_bfloat16 h0 = __float2bfloat16(x0), h1 = __float2bfloat16(x1);
    hi = packb(h0, h1);
    lo = packb(__float2bfloat16(x0 - __bfloat162float(h0)),
               __float2bfloat16(x1 - __bfloat162float(h1)));
}
__device__ __forceinline__ void cp16(void* s, const void* g) {
    uint32_t sa = (uint32_t)__cvta_generic_to_shared(s);
    asm volatile("cp.async.cg.shared.global [%0], [%1], 16;" :: "r"(sa), "l"(g));
}

// ---------------- fp32 -> bf16 hi/lo splitter ---------------------------------
__global__ __launch_bounds__(256) void split_f32(
    const float* __restrict__ in, __nv_bfloat16* __restrict__ hi,
    __nv_bfloat16* __restrict__ lo)
{
    int i = (blockIdx.x * 256 + threadIdx.x) * 4;
    float4 v = *(const float4*)(in + i);
    uint32_t h0, l0, h1, l1;
    split2(v.x, v.y, h0, l0);
    split2(v.z, v.w, h1, l1);
    uint2 H; H.x = h0; H.y = h1;
    uint2 L; L.x = l0; L.y = l1;
    *(uint2*)(hi + i) = H;
    *(uint2*)(lo + i) = L;
}

// ---------------- pipelined split-bf16 HMMA GEMM core -------------------------
#define PITCH 72
#define TILE_ELEMS (128 * PITCH)
#define BUF_ELEMS (4 * TILE_ELEMS)
#define S_GEMM (2 * BUF_ELEMS * 2)    // 147456 B (2-stage)

__device__ __forceinline__ void gemm_core(
    const __nv_bfloat16* __restrict__ Ahi, const __nv_bfloat16* __restrict__ Alo,
    const __nv_bfloat16* __restrict__ Bhi, const __nv_bfloat16* __restrict__ Blo,
    const float* __restrict__ bias, float* __restrict__ C,
    int lda, int ldb, int ldc, int K, __nv_bfloat16* sm)
{
    const int tid  = threadIdx.x;
    const int lane = tid & 31;
    const int wid  = tid >> 5;
    const int wm   = wid >> 2;
    const int wn   = wid & 3;

    float acc[4][4][4];
#pragma unroll
    for (int mt = 0; mt < 4; mt++)
#pragma unroll
        for (int nt = 0; nt < 4; nt++)
#pragma unroll
            for (int i = 0; i < 4; i++) acc[mt][nt][i] = 0.f;

    const int nch = K >> 6;

#define G_STAGE(ch, buf) do {                                              \
    __nv_bfloat16* d0 = sm + (buf) * BUF_ELEMS;                            \
    __nv_bfloat16* d1 = d0 + TILE_ELEMS;                                   \
    __nv_bfloat16* d2 = d0 + 2 * TILE_ELEMS;                               \
    __nv_bfloat16* d3 = d0 + 3 * TILE_ELEMS;                               \
    const int k0 = (ch) << 6;                                              \
    _Pragma("unroll")                                                      \
    for (int i = 0; i < 4; i++) {                                          \
        int u = i * 256 + tid;                                             \
        int r = u >> 3, kp = (u & 7) * 8, so = r * PITCH + kp;             \
        cp16(d0 + so, Ahi + (size_t)r * lda + k0 + kp);                    \
        cp16(d1 + so, Alo + (size_t)r * lda + k0 + kp);                    \
        cp16(d2 + so, Bhi + (size_t)r * ldb + k0 + kp);                    \
        cp16(d3 + so, Blo + (size_t)r * ldb + k0 + kp);                    \
    }                                                                      \
    asm volatile("cp.async.commit_group;");                                \
} while (0)

    G_STAGE(0, 0);
    for (int ch = 0; ch < nch; ch++) {
        if (ch + 1 < nch) {
            G_STAGE(ch + 1, (ch + 1) & 1);
            asm volatile("cp.async.wait_group 1;");
        } else {
            asm volatile("cp.async.wait_group 0;");
        }
        __syncthreads();

        const __nv_bfloat16* sAhi = sm + (ch & 1) * BUF_ELEMS;
        const __nv_bfloat16* sAlo = sAhi + TILE_ELEMS;
        const __nv_bfloat16* sBhi = sAhi + 2 * TILE_ELEMS;
        const __nv_bfloat16* sBlo = sAhi + 3 * TILE_ELEMS;

#pragma unroll
        for (int ks = 0; ks < 4; ks++) {
            const int kb = ks * 16 + (lane & 3) * 2;
            uint32_t bh[4][2], bl[4][2];
            const int nrow = wn * 32 + (lane >> 2);
#pragma unroll
            for (int nt = 0; nt < 4; nt++) {
                int nb = (nrow + nt * 8) * PITCH + kb;
                bh[nt][0] = *(uint32_t*)&sBhi[nb];
                bh[nt][1] = *(uint32_t*)&sBhi[nb + 8];
                bl[nt][0] = *(uint32_t*)&sBlo[nb];
                bl[nt][1] = *(uint32_t*)&sBlo[nb + 8];
            }
            const int arow = wm * 64 + (lane >> 2);
#pragma unroll
            for (int mt = 0; mt < 4; mt++) {
                int ab = (arow + mt * 16) * PITCH + kb;
                uint32_t ah[4], al[4];
                ah[0] = *(uint32_t*)&sAhi[ab];
                ah[1] = *(uint32_t*)&sAhi[ab + 8 * PITCH];
                ah[2] = *(uint32_t*)&sAhi[ab + 8];
                ah[3] = *(uint32_t*)&sAhi[ab + 8 * PITCH + 8];
                al[0] = *(uint32_t*)&sAlo[ab];
                al[1] = *(uint32_t*)&sAlo[ab + 8 * PITCH];
                al[2] = *(uint32_t*)&sAlo[ab + 8];
                al[3] = *(uint32_t*)&sAlo[ab + 8 * PITCH + 8];
#pragma unroll
                for (int nt = 0; nt < 4; nt++) {
                    mma16816(acc[mt][nt], ah, bh[nt]);
                    mma16816(acc[mt][nt], ah, bl[nt]);
                    mma16816(acc[mt][nt], al, bh[nt]);
                }
            }
        }
        __syncthreads();
    }
#undef G_STAGE

    const int r0 = wm * 64 + (lane >> 2);
    const int c0 = wn * 32 + (lane & 3) * 2;
#pragma unroll
    for (int mt = 0; mt < 4; mt++) {
#pragma unroll
        for (int nt = 0; nt < 4; nt++) {
            int cc = c0 + nt * 8;
#pragma unroll
            for (int half = 0; half < 2; half++) {
                int r = r0 + mt * 16 + half * 8;
                float2 o;
                o.x = acc[mt][nt][half * 2 + 0];
                o.y = acc[mt][nt][half * 2 + 1];
                if (bias) {
                    o.x += bias[cc];
                    o.y += bias[cc + 1];
                }
                *(float2*)(C + (size_t)r * ldc + cc) = o;
            }
        }
    }
}

// ---------------- merged QKV projection (one launch, 192 CTAs) ----------------
__global__ __launch_bounds__(256) void proj_qkv(
    const float* __restrict__ qb, const float* __restrict__ kb,
    const float* __restrict__ vb)
{
    extern __shared__ __nv_bfloat16 sm[];
    const int x = blockIdx.x;          // 0..47
    const int y = blockIdx.y;          // 0..3
    const __nv_bfloat16 *Bh, *Bl;
    const float* bias;
    float* C;
    int N, tx;
    if (x < 32)      { tx = x;      Bh = g_qwhi; Bl = g_qwlo; bias = qb; C = g_qlin; N = HDIM; }
    else if (x < 40) { tx = x - 32; Bh = g_kwhi; Bl = g_kwlo; bias = kb; C = g_klin; N = KVDIM; }
    else             { tx = x - 40; Bh = g_vwhi; Bl = g_vwlo; bias = vb; C = g_vlin; N = KVDIM; }

    const size_t arow0 = (size_t)y * 128;
    const size_t brow0 = (size_t)tx * 128;
    gemm_core(g_hshi + arow0 * HDIM, g_hslo + arow0 * HDIM,
              Bh + brow0 * HDIM, Bl + brow0 * HDIM,
              bias + brow0, C + arow0 * N + brow0,
              HDIM, HDIM, N, HDIM, sm);
}

// ---------------- generic single GEMM (O projection) --------------------------
__global__ __launch_bounds__(256) void gemm_single(
    const __nv_bfloat16* __restrict__ Ahi, const __nv_bfloat16* __restrict__ Alo,
    const __nv_bfloat16* __restrict__ Bhi, const __nv_bfloat16* __restrict__ Blo,
    const float* __restrict__ bias, float* __restrict__ C,
    int lda, int ldb, int ldc, int K)
{
    extern __shared__ __nv_bfloat16 sm[];
    const size_t arow0 = (size_t)(blockIdx.y * 128);
    const size_t brow0 = (size_t)(blockIdx.x * 128);
    gemm_core(Ahi + arow0 * lda, Alo + arow0 * lda,
              Bhi + brow0 * ldb, Blo + brow0 * ldb,
              bias ? bias + brow0 : nullptr, C + arow0 * ldc + brow0,
              lda, ldb, ldc, K, sm);
}

// ---------------- fused flash attention (2-stage cp.async pipeline) -----------
#define FK_PITCH 136
#define FV_PITCH 72
#define FBUF_ELEMS (2 * 64 * FK_PITCH + 2 * 128 * FV_PITCH)   // 35840 elems
#define S_FLASH (2 * FBUF_ELEMS * 2)                          // 143360 B

__global__ __launch_bounds__(256, 1) void flash_attn()
{
    extern __shared__ __nv_bfloat16 fsm[];

    const int bh = blockIdx.x;
    const int b = bh >> 5, h = bh & 31, kvh = h >> 2;
    const int bk = b * NKVH + kvh;
    const int tid = threadIdx.x, lane = tid & 31, w = tid >> 5;
    const int rq = w * 16 + (lane >> 2);
    const int q2 = (lane & 3) * 2;
    const float isq = 0.08838834764831845f;

    const float* Q = g_q + (size_t)bh * QLEN * DHEAD;
    uint32_t qhi[8][4], qlo[8][4];
#pragma unroll
    for (int kk = 0; kk < 8; kk++) {
#pragma unroll
        for (int f = 0; f < 4; f++) {
            int rr = rq + ((f & 1) ? 8 : 0);
            int kc = kk * 16 + ((f & 2) ? 8 : 0) + q2;
            split2(Q[rr * DHEAD + kc], Q[rr * DHEAD + kc + 1], qhi[kk][f], qlo[kk][f]);
        }
    }

    const __nv_bfloat16* Khi = g_khi + (size_t)bk * KVSEQ * DHEAD;
    const __nv_bfloat16* Klo = g_klo + (size_t)bk * KVSEQ * DHEAD;
    const __nv_bfloat16* Vhi = g_vthi + (size_t)bk * DHEAD * KVSEQ;
    const __nv_bfloat16* Vlo = g_vtlo + (size_t)bk * DHEAD * KVSEQ;

    float m0 = NEGF, m1 = NEGF, l0 = 0.f, l1 = 0.f;
    float oacc[16][4];
#pragma unroll
    for (int td = 0; td < 16; td++)
#pragma unroll
        for (int i = 0; i < 4; i++) oacc[td][i] = 0.f;

#define F_STAGE(j, buf) do {                                               \
    __nv_bfloat16* dKhi = fsm + (buf) * FBUF_ELEMS;                        \
    __nv_bfloat16* dKlo = dKhi + 64 * FK_PITCH;                            \
    __nv_bfloat16* dVhi = dKhi + 2 * 64 * FK_PITCH;                        \
    __nv_bfloat16* dVlo = dVhi + 128 * FV_PITCH;                           \
    _Pragma("unroll")                                                      \
    for (int i = 0; i < 4; i++) {                                          \
        int u = i * 256 + tid;                                             \
        int n = u >> 4, kp = (u & 15) * 8;                                 \
        size_t go = (size_t)((j) * 64 + n) * DHEAD + kp;                   \
        cp16(dKhi + n * FK_PITCH + kp, Khi + go);                          \
        cp16(dKlo + n * FK_PITCH + kp, Klo + go);                          \
        int d = u >> 3, vp = (u & 7) * 8;                                  \
        size_t gv = (size_t)d * KVSEQ + (j) * 64 + vp;                     \
        cp16(dVhi + d * FV_PITCH + vp, Vhi + gv);                          \
        cp16(dVlo + d * FV_PITCH + vp, Vlo + gv);                          \
    }                                                                      \
    asm volatile("cp.async.commit_group;");                                \
} while (0)

    F_STAGE(0, 0);
    for (int j = 0; j < NBLK; j++) {
        if (j + 1 < NBLK) {
            F_STAGE(j + 1, (j + 1) & 1);
            asm volatile("cp.async.wait_group 1;");
        } else {
            asm volatile("cp.async.wait_group 0;");
        }
        __syncthreads();

        const __nv_bfloat16* sKhi = fsm + (j & 1) * FBUF_ELEMS;
        const __nv_bfloat16* sKlo = sKhi + 64 * FK_PITCH;
        const __nv_bfloat16* sVhi = sKhi + 2 * 64 * FK_PITCH;
        const __nv_bfloat16* sVlo = sVhi + 128 * FV_PITCH;

        float sacc[8][4];
#pragma unroll
        for (int nt = 0; nt < 8; nt++)
#pragma unroll
            for (int i = 0; i < 4; i++) sacc[nt][i] = 0.f;

#pragma unroll
        for (int kk = 0; kk < 8; kk++) {
            const int kb = kk * 16 + q2;
#pragma unroll
            for (int nt = 0; nt < 8; nt++) {
                int nb = (nt * 8 + (lane >> 2)) * FK_PITCH + kb;
                uint32_t bhf[2], blf[2];
                bhf[0] = *(uint32_t*)&sKhi[nb];
                bhf[1] = *(uint32_t*)&sKhi[nb + 8];
                blf[0] = *(uint32_t*)&sKlo[nb];
                blf[1] = *(uint32_t*)&sKlo[nb + 8];
                mma16816(sacc[nt], qhi[kk], bhf);
                mma16816(sacc[nt], qhi[kk], blf);
                mma16816(sacc[nt], qlo[kk], bhf);
            }
        }

#pragma unroll
        for (int nt = 0; nt < 8; nt++)
#pragma unroll
            for (int i = 0; i < 4; i++) sacc[nt][i] *= isq;
        if (j >= 66) {
            int jc = j * 64 - PASTLEN;
#pragma unroll
            for (int nt = 0; nt < 8; nt++) {
                int c = jc + nt * 8 + q2;
                if (c     > rq)     sacc[nt][0] = NEGF;
                if (c + 1 > rq)     sacc[nt][1] = NEGF;
                if (c     > rq + 8) sacc[nt][2] = NEGF;
                if (c + 1 > rq + 8) sacc[nt][3] = NEGF;
            }
        }

        float mx0 = NEGF, mx1 = NEGF;
#pragma unroll
        for (int nt = 0; nt < 8; nt++) {
            mx0 = fmaxf(mx0, fmaxf(sacc[nt][0], sacc[nt][1]));
            mx1 = fmaxf(mx1, fmaxf(sacc[nt][2], sacc[nt][3]));
        }
        mx0 = fmaxf(mx0, __shfl_xor_sync(0xffffffffu, mx0, 1));
        mx0 = fmaxf(mx0, __shfl_xor_sync(0xffffffffu, mx0, 2));
        mx1 = fmaxf(mx1, __shfl_xor_sync(0xffffffffu, mx1, 1));
        mx1 = fmaxf(mx1, __shfl_xor_sync(0xffffffffu, mx1, 2));

        float mn0 = fmaxf(m0, mx0), mn1 = fmaxf(m1, mx1);
        float a0 = __expf(m0 - mn0), a1 = __expf(m1 - mn1);

        float rs0 = 0.f, rs1 = 0.f;
#pragma unroll
        for (int nt = 0; nt < 8; nt++) {
            sacc[nt][0] = __expf(sacc[nt][0] - mn0);
            sacc[nt][1] = __expf(sacc[nt][1] - mn0);
            sacc[nt][2] = __expf(sacc[nt][2] - mn1);
            sacc[nt][3] = __expf(sacc[nt][3] - mn1);
            rs0 += sacc[nt][0] + sacc[nt][1];
            rs1 += sacc[nt][2] + sacc[nt][3];
        }
        rs0 += __shfl_xor_sync(0xffffffffu, rs0, 1);
        rs0 += __shfl_xor_sync(0xffffffffu, rs0, 2);
        rs1 += __shfl_xor_sync(0xffffffffu, rs1, 1);
        rs1 += __shfl_xor_sync(0xffffffffu, rs1, 2);
        l0 = l0 * a0 + rs0;
        l1 = l1 * a1 + rs1;
        m0 = mn0; m1 = mn1;

#pragma unroll
        for (int td = 0; td < 16; td++) {
            oacc[td][0] *= a0; oacc[td][1] *= a0;
            oacc[td][2] *= a1; oacc[td][3] *= a1;
        }

#pragma unroll
        for (int kk2 = 0; kk2 < 4; kk2++) {
            uint32_t phi[4], plo[4];
            split2(sacc[2 * kk2][0],     sacc[2 * kk2][1],     phi[0], plo[0]);
            split2(sacc[2 * kk2][2],     sacc[2 * kk2][3],     phi[1], plo[1]);
            split2(sacc[2 * kk2 + 1][0], sacc[2 * kk2 + 1][1], phi[2], plo[2]);
            split2(sacc[2 * kk2 + 1][2], sacc[2 * kk2 + 1][3], phi[3], plo[3]);
            const int kb = kk2 * 16 + q2;
#pragma unroll
            for (int td = 0; td < 16; td++) {
                int vb = (td * 8 + (lane >> 2)) * FV_PITCH + kb;
                uint32_t vbh[2], vbl[2];
                vbh[0] = *(uint32_t*)&sVhi[vb];
                vbh[1] = *(uint32_t*)&sVhi[vb + 8];
                vbl[0] = *(uint32_t*)&sVlo[vb];
                vbl[1] = *(uint32_t*)&sVlo[vb + 8];
                mma16816(oacc[td], phi, vbh);
                mma16816(oacc[td], phi, vbl);
                mma16816(oacc[td], plo, vbh);
            }
        }
        __syncthreads();
    }
#undef F_STAGE

    float inv0 = 1.f / l0, inv1 = 1.f / l1;
#pragma unroll
    for (int td = 0; td < 16; td++) {
        int cd = h * DHEAD + td * 8 + q2;
        {
            float x0 = oacc[td][0] * inv0, x1 = oacc[td][1] * inv0;
            uint32_t hi, lo;
            split2(x0, x1, hi, lo);
            size_t o = (size_t)(b * QLEN + rq) * HDIM + cd;
            *(uint32_t*)&g_aohi[o] = hi;
            *(uint32_t*)&g_aolo[o] = lo;
        }
        {
            float x0 = oacc[td][2] * inv1, x1 = oacc[td][3] * inv1;
            uint32_t hi, lo;
            split2(x0, x1, hi, lo);
            size_t o = (size_t)(b * QLEN + rq + 8) * HDIM + cd;
            *(uint32_t*)&g_aohi[o] = hi;
            *(uint32_t*)&g_aolo[o] = lo;
        }
    }
}

// ---------------- RoPE Q ------------------------------------------------------
__global__ __launch_bounds__(256) void rope_q_kernel()
{
    int idx = blockIdx.x * 256 + threadIdx.x;
    int d = idx & 127;
    int t = (idx >> 7) & 127;
    int h = (idx >> 14) & 31;
    int b = idx >> 19;
    size_t base = ((size_t)(b * QLEN + t)) * HDIM + (size_t)h * DHEAD;
    int i = d & 63;
    float inv = 1.0f / powf(1.0e6f, (float)(2 * i) / 128.0f);
    float ang = (float)(PASTLEN + t) * inv;
    float s, c;
    sincosf(ang, &s, &c);
    float x  = g_qlin[base + d];
    float xo = g_qlin[base + ((d < 64) ? d + 64 : d - 64)];
    g_q[idx] = (d < 64) ? (x * c - xo * s) : (x * c + xo * s);
}

// ---------------- RoPE K new tokens -> split K cache --------------------------
__global__ __launch_bounds__(256) void rope_k_kernel()
{
    int idx = blockIdx.x * 256 + threadIdx.x;      // 4*8*128*128
    int d   = idx & 127;
    int t   = (idx >> 7) & 127;
    int kvh = (idx >> 14) & 7;
    int b   = idx >> 17;
    size_t base = ((size_t)(b * QLEN + t)) * KVDIM + (size_t)kvh * DHEAD;
    int i = d & 63;
    float inv = 1.0f / powf(1.0e6f, (float)(2 * i) / 128.0f);
    float ang = (float)(PASTLEN + t) * inv;
    float s, c;
    sincosf(ang, &s, &c);
    float x  = g_klin[base + d];
    float xo = g_klin[base + ((d < 64) ? d + 64 : d - 64)];
    float v  = (d < 64) ? (x * c - xo * s) : (x * c + xo * s);
    size_t o = (((size_t)(b * NKVH + kvh)) * KVSEQ + PASTLEN + t) * DHEAD + d;
    __nv_bfloat16 hi = __float2bfloat16(v);
    g_khi[o] = hi;
    g_klo[o] = __float2bfloat16(v - __bfloat162float(hi));
}

// ---------------- V new tokens -> split V^T cache -----------------------------
__global__ __launch_bounds__(256) void v_scatter_kernel()
{
    int idx = blockIdx.x * 256 + threadIdx.x;      // t inner
    int t   = idx & 127;
    int d   = (idx >> 7) & 127;
    int kvh = (idx >> 14) & 7;
    int b   = idx >> 17;
    float v = g_vlin[((size_t)(b * QLEN + t)) * KVDIM + kvh * DHEAD + d];
    size_t o = ((size_t)(b * NKVH + kvh) * DHEAD + d) * KVSEQ + PASTLEN + t;
    __nv_bfloat16 hi = __float2bfloat16(v);
    g_vthi[o] = hi;
    g_vtlo[o] = __float2bfloat16(v - __bfloat162float(hi));
}

// ---------------- fp32 past copy (split) --------------------------------------
__global__ __launch_bounds__(256) void past_copy_kernel(
    const float* __restrict__ kfp, const float* __restrict__ vfp)
{
    int idx = blockIdx.x * 256 + threadIdx.x;      // 32*128*128
    int d  = idx & 127;
    int r  = (idx >> 7) & 127;
    int bk = idx >> 14;
    size_t src = ((size_t)bk * RESLEN + r) * DHEAD + d;
    if (blockIdx.y == 0) {
        float v = kfp[src];
        size_t o = ((size_t)bk * KVSEQ + NQK + r) * DHEAD + d;
        __nv_bfloat16 hi = __float2bfloat16(v);
        g_khi[o] = hi;
        g_klo[o] = __float2bfloat16(v - __bfloat162float(hi));
    } else {
        float v = vfp[src];
        size_t o = ((size_t)bk * DHEAD + d) * KVSEQ + NQK + r;
        __nv_bfloat16 hi = __float2bfloat16(v);
        g_vthi[o] = hi;
        g_vtlo[o] = __float2bfloat16(v - __bfloat162float(hi));
    }
}

// ---------------- dequant 2-bit K -> split K cache ----------------------------
__global__ __launch_bounds__(256) void dequant_k_kernel(
    const int* __restrict__ kq, const float* __restrict__ ks,
    const float* __restrict__ km)
{
    int idx = blockIdx.x * 256 + threadIdx.x;      // d inner
    int d  = idx & 127;
    int n  = (idx >> 7) & 4095;
    int bk = idx >> 19;
    unsigned word = (unsigned)kq[((size_t)bk * DHEAD + d) * (NQK / 16) + (n >> 4)];
    float code = (float)((word >> ((n & 15) * 2)) & 3u);
    size_t sidx = ((size_t)bk * DHEAD + d) * (NQK / 64) + (n >> 6);
    float v = code * ks[sidx] + km[sidx];
    size_t o = ((size_t)bk * KVSEQ + n) * DHEAD + d;
    __nv_bfloat16 hi = __float2bfloat16(v);
    g_khi[o] = hi;
    g_klo[o] = __float2bfloat16(v - __bfloat162float(hi));
}

// ---------------- dequant 2-bit V -> split V^T cache --------------------------
__global__ __launch_bounds__(256) void dequant_v_kernel(
    const int* __restrict__ vq, const float* __restrict__ vs,
    const float* __restrict__ vm)
{
    int idx = blockIdx.x * 256 + threadIdx.x;      // n inner
    int n  = idx & 4095;
    int d  = (idx >> 12) & 127;
    int bk = idx >> 19;
    unsigned word = (unsigned)vq[((size_t)bk * NQK + n) * (DHEAD / 16) + (d >> 4)];
    float code = (float)((word >> ((d & 15) * 2)) & 3u);
    size_t sidx = ((size_t)bk * NQK + n) * (DHEAD / 64) + (d >> 6);
    float v = code * vs[sidx] + vm[sidx];
    size_t o = ((size_t)bk * DHEAD + d) * KVSEQ + n;
    __nv_bfloat16 hi = __float2bfloat16(v);
    g_vthi[o] = hi;
    g_vtlo[o] = __float2bfloat16(v - __bfloat162float(hi));
}

// ---------------- host launch --------------------------------------------------
extern "C" void kernel_launch(void* const* d_in, const int* in_sizes, int n_in,
                              void* d_out, int out_size)
{
    (void)in_sizes; (void)n_in; (void)out_size;
    const float* hs  = (const float*)d_in[0];
    const float* qw  = (const float*)d_in[1];
    const float* qb  = (const float*)d_in[2];
    const float* kw  = (const float*)d_in[3];
    const float* kb  = (const float*)d_in[4];
    const float* vw  = (const float*)d_in[5];
    const float* vb  = (const float*)d_in[6];
    const float* ow  = (const float*)d_in[7];
    const int*   kqt = (const int*)  d_in[8];
    const float* kst = (const float*)d_in[9];
    const float* kmt = (const float*)d_in[10];
    const float* kfp = (const float*)d_in[11];
    const int*   vq  = (const int*)  d_in[12];
    const float* vs  = (const float*)d_in[13];
    const float* vm  = (const float*)d_in[14];
    const float* vfp = (const float*)d_in[15];
    float* out = (float*)d_out;

    __nv_bfloat16 *hshi, *hslo, *qwhi, *qwlo, *kwhi, *kwlo, *vwhi, *vwlo;
    __nv_bfloat16 *owhi, *owlo, *aohi, *aolo;
    cudaGetSymbolAddress((void**)&hshi, g_hshi);
    cudaGetSymbolAddress((void**)&hslo, g_hslo);
    cudaGetSymbolAddress((void**)&qwhi, g_qwhi);
    cudaGetSymbolAddress((void**)&qwlo, g_qwlo);
    cudaGetSymbolAddress((void**)&kwhi, g_kwhi);
    cudaGetSymbolAddress((void**)&kwlo, g_kwlo);
    cudaGetSymbolAddress((void**)&vwhi, g_vwhi);
    cudaGetSymbolAddress((void**)&vwlo, g_vwlo);
    cudaGetSymbolAddress((void**)&owhi, g_owhi);
    cudaGetSymbolAddress((void**)&owlo, g_owlo);
    cudaGetSymbolAddress((void**)&aohi, g_aohi);
    cudaGetSymbolAddress((void**)&aolo, g_aolo);

    cudaFuncSetAttribute(proj_qkv,    cudaFuncAttributeMaxDynamicSharedMemorySize, S_GEMM);
    cudaFuncSetAttribute(gemm_single, cudaFuncAttributeMaxDynamicSharedMemorySize, S_GEMM);
    cudaFuncSetAttribute(flash_attn,  cudaFuncAttributeMaxDynamicSharedMemorySize, S_FLASH);

    dim3 blk(256);

    // operand pre-split
    split_f32<<<(TOK * HDIM) / 1024, blk>>>(hs, hshi, hslo);
    split_f32<<<(HDIM * HDIM) / 1024, blk>>>(qw, qwhi, qwlo);
    split_f32<<<(KVDIM * HDIM) / 1024, blk>>>(kw, kwhi, kwlo);
    split_f32<<<(KVDIM * HDIM) / 1024, blk>>>(vw, vwhi, vwlo);
    split_f32<<<(HDIM * HDIM) / 1024, blk>>>(ow, owhi, owlo);

    // merged QKV projections (192 CTAs, pipelined)
    proj_qkv<<<dim3(48, 4), blk, S_GEMM>>>(qb, kb, vb);

    // RoPE + cache assembly
    rope_q_kernel<<<(TOK * HDIM) / 256, blk>>>();
    rope_k_kernel<<<(TOK * KVDIM) / 256, blk>>>();
    v_scatter_kernel<<<(TOK * KVDIM) / 256, blk>>>();
    past_copy_kernel<<<dim3((32 * RESLEN * DHEAD) / 256, 2), blk>>>(kfp, vfp);
    dequant_k_kernel<<<(32 * NQK * DHEAD) / 256, blk>>>(kqt, kst, kmt);
    dequant_v_kernel<<<(32 * NQK * DHEAD) / 256, blk>>>(vq, vs, vm);

    // fused attention
    flash_attn<<<BATCH * NHEAD, blk, S_FLASH>>>();

    // output projection (pipelined)
    gemm_single<<<dim3(32, 4), blk, S_GEMM>>>(aohi, aolo, owhi, owlo, nullptr, out, HDIM, HDIM, HDIM, HDIM);
}